// round 10
// baseline (speedup 1.0000x reference)
#include <cuda_runtime.h>
#include <cuda_fp16.h>
#include <math.h>
#include <stdint.h>

// Problem constants (B=2, S=2048, D=2048, H=16, HD=128)
#define S_LEN 2048
#define DMODEL 2048
#define NH 16
#define HDIM 128
#define BATCH 2
#define NTOK (BATCH * S_LEN)   // 4096

// ---------------------------------------------------------------------------
// Scratch (__device__ globals; allocation-free rule)
// ---------------------------------------------------------------------------
__device__ __half g_xh[(size_t)NTOK * DMODEL];    // x fp16
__device__ __half g_qh[(size_t)NTOK * DMODEL];    // roped Q fp16
__device__ __half g_kh[(size_t)NTOK * DMODEL];    // roped K fp16
__device__ __half g_vh[(size_t)NTOK * DMODEL];    // V fp16
__device__ __half g_aoh[(size_t)NTOK * DMODEL];   // attention out fp16
__device__ __half g_Wqh[(size_t)DMODEL * DMODEL];
__device__ __half g_Wkh[(size_t)DMODEL * DMODEL];
__device__ __half g_Wvh[(size_t)DMODEL * DMODEL];
__device__ __half g_Woh[(size_t)DMODEL * DMODEL];
__device__ float2 g_sc[(size_t)S_LEN * 64];       // (sin, cos) table

// ---------------------------------------------------------------------------
// Helpers
// ---------------------------------------------------------------------------
__device__ __forceinline__ uint32_t packh2(float a, float b) {
    __half2 h = __floats2half2_rn(a, b);
    return *(uint32_t*)&h;
}
__device__ __forceinline__ void mma_f16(float* c, const uint32_t* a,
                                        const uint32_t* b) {
    asm volatile(
        "mma.sync.aligned.m16n8k16.row.col.f32.f16.f16.f32 "
        "{%0,%1,%2,%3}, {%4,%5,%6,%7}, {%8,%9}, {%0,%1,%2,%3};"
        : "+f"(c[0]), "+f"(c[1]), "+f"(c[2]), "+f"(c[3])
        : "r"(a[0]), "r"(a[1]), "r"(a[2]), "r"(a[3]), "r"(b[0]), "r"(b[1]));
}
__device__ __forceinline__ uint32_t smem_u32(const void* p) {
    return (uint32_t)__cvta_generic_to_shared(p);
}
__device__ __forceinline__ void cp16(uint32_t dst, const void* src) {
    asm volatile("cp.async.cg.shared.global [%0], [%1], 16;"
                 :: "r"(dst), "l"(src));
}
__device__ __forceinline__ void cp_commit() {
    asm volatile("cp.async.commit_group;");
}
template <int N>
__device__ __forceinline__ void cp_wait() {
    asm volatile("cp.async.wait_group %0;" :: "n"(N));
}
__device__ __forceinline__ void ldsm4(uint32_t& r0, uint32_t& r1,
                                      uint32_t& r2, uint32_t& r3,
                                      uint32_t addr) {
    asm volatile("ldmatrix.sync.aligned.m8n8.x4.shared.b16 {%0,%1,%2,%3}, [%4];"
                 : "=r"(r0), "=r"(r1), "=r"(r2), "=r"(r3) : "r"(addr));
}
__device__ __forceinline__ void ldsm4t(uint32_t& r0, uint32_t& r1,
                                       uint32_t& r2, uint32_t& r3,
                                       uint32_t addr) {
    asm volatile("ldmatrix.sync.aligned.m8n8.x4.trans.shared.b16 {%0,%1,%2,%3}, [%4];"
                 : "=r"(r0), "=r"(r1), "=r"(r2), "=r"(r3) : "r"(addr));
}

// ---------------------------------------------------------------------------
// Small prep kernels
// ---------------------------------------------------------------------------
__global__ void __launch_bounds__(256) sincos_kernel(float2* __restrict__ T)
{
    const int idx = blockIdx.x * blockDim.x + threadIdx.x;   // 2048*64
    const int j = idx & 63;
    const int pos = idx >> 6;
    const double inv = exp(-(double)j * (9.210340371976184 / 64.0));
    const float ang = (float)((double)pos * inv);
    float sn, cs;
    sincosf(ang, &sn, &cs);
    T[idx] = make_float2(sn, cs);
}

__global__ void __launch_bounds__(256) conv_h_kernel(
    const float* __restrict__ X, __half* __restrict__ H, int n2)
{
    int i = blockIdx.x * blockDim.x + threadIdx.x;
    if (i >= n2) return;
    float2 v = ((const float2*)X)[i];
    ((uint32_t*)H)[i] = packh2(v.x, v.y);
}

// 4 weights at once (grid.z selects); W fp32 [K][N] -> fp16 [N][K]
__global__ void __launch_bounds__(256) transpose4_h_kernel(
    const float* __restrict__ W0, const float* __restrict__ W1,
    const float* __restrict__ W2, const float* __restrict__ W3,
    __half* __restrict__ T0, __half* __restrict__ T1,
    __half* __restrict__ T2, __half* __restrict__ T3, int K, int N)
{
    __shared__ float t[32][33];
    const int z = blockIdx.z;
    const float* W = (z == 0) ? W0 : (z == 1) ? W1 : (z == 2) ? W2 : W3;
    __half* Th = (z == 0) ? T0 : (z == 1) ? T1 : (z == 2) ? T2 : T3;
    const int k0 = blockIdx.x * 32;
    const int n0 = blockIdx.y * 32;
    const int tx = threadIdx.x & 31;
    const int ty = threadIdx.x >> 5;
#pragma unroll
    for (int i = 0; i < 4; ++i)
        t[ty + 8 * i][tx] = W[(size_t)(k0 + ty + 8 * i) * N + n0 + tx];
    __syncthreads();
#pragma unroll
    for (int i = 0; i < 4; ++i) {
        const int n = n0 + ty + 8 * i;
        Th[(size_t)n * K + k0 + tx] = __float2half_rn(t[tx][ty + 8 * i]);
    }
}

// ---------------------------------------------------------------------------
// fp16 GEMM v3: CTA tile 256x128x64, 512 threads (16 warps, 4m x 4n),
// warp tile 64x32 (identical per-warp math to v2 -> bit-identical results).
// 3 cp.async stages x 48KB = 144KB smem, 1 CTA/SM (regfile-bound anyway).
// Epilogues: Cf -> fp32; sel==2 -> fp16 (V); sel 0/1 -> fused RoPE fp16 Q/K.
// ---------------------------------------------------------------------------
#define G_STAGE 49152                 // A 32KB + B 16KB
#define G_SMEM  (3 * G_STAGE)         // 147456

__global__ void __launch_bounds__(512, 1) hgemm1_kernel(
    const __half* __restrict__ Ah,
    const __half* __restrict__ B0, const __half* __restrict__ B1,
    const __half* __restrict__ B2,
    __half* __restrict__ Qout, __half* __restrict__ Kout,
    __half* __restrict__ Vout, float* __restrict__ Cf,
    const float2* __restrict__ T,
    int M, int N, int K)
{
    extern __shared__ char smem[];
    const uint32_t sbase = smem_u32(smem);

    const int tid = threadIdx.x;
    const int wid = tid >> 5;
    const int lane = tid & 31;
    const int g = lane >> 2;
    const int tig = lane & 3;
    const int warp_m = wid >> 2;        // 0..3
    const int warp_n = wid & 3;         // 0..3
    const int row0 = blockIdx.y * 256;
    const int sel = blockIdx.x >> 4;
    const int col0 = (blockIdx.x & 15) * 128;

    const __half* Bt = (sel == 0) ? B0 : (sel == 1) ? B1 : B2;
    const __half* srcs[2] = { Ah + (size_t)row0 * K, Bt + (size_t)col0 * K };

    const int ntiles = K >> 6;   // 32

    // fill k-tile kt into stage kt%3: A 2048 chunks + B 1024 chunks
    auto fill = [&](int kt) {
        const uint32_t sb = sbase + (kt % 3) * G_STAGE;
        const int k0 = kt << 6;
#pragma unroll
        for (int it = 0; it < 6; ++it) {
            const int idx = tid + it * 512;          // 0..3071
            const int arr = idx >> 11;               // 0:A (2048) 1:B (1024)
            const int i = idx & 2047;
            const int r = i >> 3;
            const int ch = i & 7;
            cp16(sb + arr * 32768 + r * 128 + ((ch ^ (r & 7)) << 4),
                 srcs[arr] + (size_t)r * K + k0 + ch * 8);
        }
    };

    fill(0); cp_commit();
    fill(1); cp_commit();

    float acc[4][4][4];
#pragma unroll
    for (int mf = 0; mf < 4; ++mf)
#pragma unroll
        for (int nf = 0; nf < 4; ++nf)
#pragma unroll
            for (int r = 0; r < 4; ++r) acc[mf][nf][r] = 0.0f;

    const int a_row = (lane & 7) + ((lane >> 3) & 1) * 8;
    const int a_chs = (lane >> 4) & 1;
    const int b_row = (lane & 7) + ((lane >> 4) & 1) * 8;
    const int b_chs = (lane >> 3) & 1;

    for (int kt = 0; kt < ntiles; ++kt) {
        cp_wait<1>();
        __syncthreads();

        const uint32_t sA = sbase + (kt % 3) * G_STAGE;
        const uint32_t sB = sA + 32768;

#pragma unroll
        for (int ks = 0; ks < 4; ++ks) {
            uint32_t bh[4][2];
#pragma unroll
            for (int nb = 0; nb < 2; ++nb) {
                const int r = warp_n * 32 + nb * 16 + b_row;
                const int ch = 2 * ks + b_chs;
                ldsm4(bh[2*nb][0], bh[2*nb][1], bh[2*nb+1][0], bh[2*nb+1][1],
                      sB + r * 128 + ((ch ^ (r & 7)) << 4));
            }
#pragma unroll
            for (int mf = 0; mf < 4; ++mf) {
                const int r = warp_m * 64 + mf * 16 + a_row;
                const int ch = 2 * ks + a_chs;
                uint32_t af[4];
                ldsm4(af[0], af[1], af[2], af[3],
                      sA + r * 128 + ((ch ^ (r & 7)) << 4));
#pragma unroll
                for (int nf = 0; nf < 4; ++nf)
                    mma_f16(acc[mf][nf], af, bh[nf]);
            }
        }

        __syncthreads();
        if (kt + 2 < ntiles) fill(kt + 2);
        cp_commit();
    }

    if (Cf) {
        // fp32 epilogue (output projection)
#pragma unroll
        for (int mf = 0; mf < 4; ++mf) {
            const int row = row0 + warp_m * 64 + mf * 16 + g;
#pragma unroll
            for (int nf = 0; nf < 4; ++nf) {
                const int col = col0 + warp_n * 32 + nf * 8 + 2 * tig;
                *(float2*)&Cf[(size_t)row * N + col] =
                    make_float2(acc[mf][nf][0], acc[mf][nf][1]);
                *(float2*)&Cf[(size_t)(row + 8) * N + col] =
                    make_float2(acc[mf][nf][2], acc[mf][nf][3]);
            }
        }
    } else if (sel == 2) {
        // V: fp16 plane
#pragma unroll
        for (int mf = 0; mf < 4; ++mf) {
            const int row = row0 + warp_m * 64 + mf * 16 + g;
#pragma unroll
            for (int nf = 0; nf < 4; ++nf) {
                const int col = col0 + warp_n * 32 + nf * 8 + 2 * tig;
                *(uint32_t*)&Vout[(size_t)row * N + col] =
                    packh2(acc[mf][nf][0], acc[mf][nf][1]);
                *(uint32_t*)&Vout[(size_t)(row + 8) * N + col] =
                    packh2(acc[mf][nf][2], acc[mf][nf][3]);
            }
        }
    } else {
        // Q/K: fused RoPE via smem staging (256 rows x 132 fp32 = 135KB)
        __syncthreads();   // all warps done reading pipeline stages
        float* st = (float*)smem;
#pragma unroll
        for (int mf = 0; mf < 4; ++mf) {
            const int r1 = warp_m * 64 + mf * 16 + g;
#pragma unroll
            for (int nf = 0; nf < 4; ++nf) {
                const int c = warp_n * 32 + nf * 8 + 2 * tig;
                st[r1 * 132 + c]           = acc[mf][nf][0];
                st[r1 * 132 + c + 1]       = acc[mf][nf][1];
                st[(r1 + 8) * 132 + c]     = acc[mf][nf][2];
                st[(r1 + 8) * 132 + c + 1] = acc[mf][nf][3];
            }
        }
        __syncthreads();
        __half* Ch = (sel == 0) ? Qout : Kout;
#pragma unroll
        for (int p = 0; p < 16; ++p) {
            const int idx = tid + 512 * p;   // 0..8191
            const int r = idx >> 5;          // 0..255
            const int j = (idx & 31) * 2;    // 0..62
            const float a0 = st[r * 132 + j];
            const float a1 = st[r * 132 + j + 1];
            const float b0 = st[r * 132 + j + 64];
            const float b1 = st[r * 132 + j + 65];
            const int pos = (row0 + r) & (S_LEN - 1);
            const float2 s0 = T[pos * 64 + j];
            const float2 s1 = T[pos * 64 + j + 1];
            const float o00 = a0 * s0.y - b0 * s0.x;
            const float o10 = b0 * s0.y + a0 * s0.x;
            const float o01 = a1 * s1.y - b1 * s1.x;
            const float o11 = b1 * s1.y + a1 * s1.x;
            const size_t rb = (size_t)(row0 + r) * N + col0;
            *(uint32_t*)&Ch[rb + j]      = packh2(o00, o01);
            *(uint32_t*)&Ch[rb + j + 64] = packh2(o10, o11);
        }
    }
}

// ---------------------------------------------------------------------------
// Flash attention, fp16 single-term (causal, tanh-cap 50, sink logit 0).
// K/V double-buffered via cp.async; V row-major + ldmatrix.trans for PV.
// CTA: 128 q-rows x kv-tiles of 64; 8 warps; warp = 16 q-rows; occ 2.
// ---------------------------------------------------------------------------
#define FQ 0
#define FK 8704                            // 2 x (64 rows x 68 words)
#define FV (FK + 2 * 64 * 68)              // 2 x (64 rows x 64 words)
#define FLASH_WORDS (FV + 2 * 64 * 64)     // 25600 words
#define FLASH_SMEM (FLASH_WORDS * 4)       // 102400 bytes

__global__ void __launch_bounds__(256, 2) flash_mma_kernel(
    const __half* __restrict__ Q, const __half* __restrict__ K,
    const __half* __restrict__ V, __half* __restrict__ O)
{
    extern __shared__ uint32_t sf[];
    uint32_t* Qs = sf + FQ;
    const uint32_t sbase = smem_u32(sf);

    const int qb = gridDim.x - 1 - blockIdx.x;
    const int h = blockIdx.y;
    const int b = blockIdx.z;
    const int tid = threadIdx.x;
    const int wid = tid >> 5;
    const int lane = tid & 31;
    const int g = lane >> 2;
    const int tig = lane & 3;
    const int q0 = qb * 128;

    const float SCALE = 0.08838834764831845f;
    const float CAP = 50.0f;
    const float INV_CAP = 1.0f / 50.0f;

    const size_t hb = (size_t)b * S_LEN * DMODEL + (size_t)h * HDIM;
    const __half* Qg = Q + hb;
    const __half* Kg = K + hb;
    const __half* Vg = V + hb;

    auto fillKV = [&](int kb) {
        const int k0 = kb * 64;
        const int buf = kb & 1;
        const uint32_t kb_s = sbase + (FK + buf * 64 * 68) * 4;
        const uint32_t vb_s = sbase + (FV + buf * 64 * 64) * 4;
#pragma unroll
        for (int it = 0; it < 4; ++it) {
            const int i = tid + it * 256;        // 0..1023
            const int r = i >> 4;
            const int c = i & 15;
            cp16(kb_s + r * 272 + c * 16,
                 Kg + (size_t)(k0 + r) * DMODEL + c * 8);
            cp16(vb_s + r * 256 + ((c ^ (r & 7)) << 4),
                 Vg + (size_t)(k0 + r) * DMODEL + c * 8);
        }
    };

    // Q tile fill (once)
    for (int i = tid; i < 128 * 16; i += 256) {
        const int r = i >> 4;
        const int ch = i & 15;
        *(uint4*)&Qs[r * 68 + ch * 4] =
            *(const uint4*)&Qg[(size_t)(q0 + r) * DMODEL + ch * 8];
    }

    float o[16][4];
#pragma unroll
    for (int nf = 0; nf < 16; ++nf)
#pragma unroll
        for (int r = 0; r < 4; ++r) o[nf][r] = 0.0f;

    float m0 = 0.0f, m1 = 0.0f;   // sink logit 0
    float l0 = 1.0f, l1 = 1.0f;

    const int mrow0 = wid * 16 + g;
    const int kmax = 2 * qb + 1;

    fillKV(0); cp_commit();

    for (int kb = 0; kb <= kmax; ++kb) {
        cp_wait<0>();
        __syncthreads();
        if (kb < kmax) { fillKV(kb + 1); cp_commit(); }

        const int k0 = kb * 64;
        const int buf = kb & 1;
        const uint32_t* Ks = sf + FK + buf * 64 * 68;
        const uint32_t vb_s = sbase + (FV + buf * 64 * 64) * 4;

        // S = Q K^T
        float s[8][4];
#pragma unroll
        for (int nf = 0; nf < 8; ++nf)
#pragma unroll
            for (int r = 0; r < 4; ++r) s[nf][r] = 0.0f;

#pragma unroll
        for (int ks = 0; ks < 8; ++ks) {
            const int kw = 8 * ks + tig;
            uint32_t ah[4];
            const int ra = (wid * 16 + g) * 68;
            const int rb = (wid * 16 + g + 8) * 68;
            ah[0] = Qs[ra + kw];     ah[1] = Qs[rb + kw];
            ah[2] = Qs[ra + kw + 4]; ah[3] = Qs[rb + kw + 4];
#pragma unroll
            for (int nf = 0; nf < 8; ++nf) {
                const int n = (8 * nf + g) * 68;
                uint32_t bh[2];
                bh[0] = Ks[n + kw]; bh[1] = Ks[n + kw + 4];
                mma_f16(s[nf], ah, bh);
            }
        }

        // scale, tanh-cap, causal mask
        const bool need_mask = (kb >= 2 * qb);
        const int grow0 = q0 + mrow0;
        const int grow1 = grow0 + 8;
#pragma unroll
        for (int nf = 0; nf < 8; ++nf) {
#pragma unroll
            for (int r = 0; r < 4; ++r) {
                float v = s[nf][r] * SCALE;
                v = CAP * tanhf(v * INV_CAP);
                if (need_mask) {
                    const int col = k0 + 8 * nf + 2 * tig + (r & 1);
                    const int row = (r < 2) ? grow0 : grow1;
                    if (col > row) v = -INFINITY;
                }
                s[nf][r] = v;
            }
        }

        // online softmax
        float rmax0 = -3.4e38f, rmax1 = -3.4e38f;
#pragma unroll
        for (int nf = 0; nf < 8; ++nf) {
            rmax0 = fmaxf(rmax0, fmaxf(s[nf][0], s[nf][1]));
            rmax1 = fmaxf(rmax1, fmaxf(s[nf][2], s[nf][3]));
        }
#pragma unroll
        for (int w = 1; w < 4; w <<= 1) {
            rmax0 = fmaxf(rmax0, __shfl_xor_sync(0xffffffffu, rmax0, w));
            rmax1 = fmaxf(rmax1, __shfl_xor_sync(0xffffffffu, rmax1, w));
        }
        const float mn0 = fmaxf(m0, rmax0);
        const float mn1 = fmaxf(m1, rmax1);
        const float cr0 = __expf(m0 - mn0);
        const float cr1 = __expf(m1 - mn1);
        m0 = mn0; m1 = mn1;

        float rs0 = 0.0f, rs1 = 0.0f;
#pragma unroll
        for (int nf = 0; nf < 8; ++nf) {
            s[nf][0] = __expf(s[nf][0] - mn0);
            s[nf][1] = __expf(s[nf][1] - mn0);
            s[nf][2] = __expf(s[nf][2] - mn1);
            s[nf][3] = __expf(s[nf][3] - mn1);
            rs0 += s[nf][0] + s[nf][1];
            rs1 += s[nf][2] + s[nf][3];
        }
#pragma unroll
        for (int w = 1; w < 4; w <<= 1) {
            rs0 += __shfl_xor_sync(0xffffffffu, rs0, w);
            rs1 += __shfl_xor_sync(0xffffffffu, rs1, w);
        }
        l0 = l0 * cr0 + rs0;
        l1 = l1 * cr1 + rs1;

#pragma unroll
        for (int nf = 0; nf < 16; ++nf) {
            o[nf][0] *= cr0; o[nf][1] *= cr0;
            o[nf][2] *= cr1; o[nf][3] *= cr1;
        }

        // O += P V : P rounded fp16; V fragments via ldmatrix.trans
#pragma unroll
        for (int ks = 0; ks < 4; ++ks) {
            uint32_t ah[4];
            ah[0] = packh2(s[2 * ks][0],     s[2 * ks][1]);
            ah[1] = packh2(s[2 * ks][2],     s[2 * ks][3]);
            ah[2] = packh2(s[2 * ks + 1][0], s[2 * ks + 1][1]);
            ah[3] = packh2(s[2 * ks + 1][2], s[2 * ks + 1][3]);
            const int rl = 16 * ks + (lane & 15);
#pragma unroll
            for (int nfp = 0; nfp < 8; ++nfp) {
                const int c = 2 * nfp + (lane >> 4);
                uint32_t b0a, b1a, b0b, b1b;
                ldsm4t(b0a, b1a, b0b, b1b,
                       vb_s + rl * 256 + ((c ^ (rl & 7)) << 4));
                uint32_t bA[2] = { b0a, b1a };
                uint32_t bB[2] = { b0b, b1b };
                mma_f16(o[2 * nfp],     ah, bA);
                mma_f16(o[2 * nfp + 1], ah, bB);
            }
        }
    }

    // epilogue: normalize + write fp16 AO plane
    const float inv0 = 1.0f / l0;
    const float inv1 = 1.0f / l1;
    __half* Og = O + hb;
    const int row0g = q0 + wid * 16 + g;
#pragma unroll
    for (int nf = 0; nf < 16; ++nf) {
        const int col = 8 * nf + 2 * tig;
        *(uint32_t*)&Og[(size_t)row0g * DMODEL + col] =
            packh2(o[nf][0] * inv0, o[nf][1] * inv0);
        *(uint32_t*)&Og[(size_t)(row0g + 8) * DMODEL + col] =
            packh2(o[nf][2] * inv1, o[nf][3] * inv1);
    }
}

// ---------------------------------------------------------------------------
extern "C" void kernel_launch(void* const* d_in, const int* in_sizes, int n_in,
                              void* d_out, int out_size)
{
    const float* x  = (const float*)d_in[0];
    const float* Wq = (const float*)d_in[1];
    const float* Wk = (const float*)d_in[2];
    const float* Wv = (const float*)d_in[3];
    const float* Wo = (const float*)d_in[4];
    float* out = (float*)d_out;

    __half *xh, *qh, *kh, *vh, *aoh, *wqh, *wkh, *wvh, *woh;
    float2* sc;
    cudaGetSymbolAddress((void**)&xh,  g_xh);
    cudaGetSymbolAddress((void**)&qh,  g_qh);
    cudaGetSymbolAddress((void**)&kh,  g_kh);
    cudaGetSymbolAddress((void**)&vh,  g_vh);
    cudaGetSymbolAddress((void**)&aoh, g_aoh);
    cudaGetSymbolAddress((void**)&wqh, g_Wqh);
    cudaGetSymbolAddress((void**)&wkh, g_Wkh);
    cudaGetSymbolAddress((void**)&wvh, g_Wvh);
    cudaGetSymbolAddress((void**)&woh, g_Woh);
    cudaGetSymbolAddress((void**)&sc,  g_sc);

    cudaFuncSetAttribute(hgemm1_kernel,
                         cudaFuncAttributeMaxDynamicSharedMemorySize, G_SMEM);
    cudaFuncSetAttribute(flash_mma_kernel,
                         cudaFuncAttributeMaxDynamicSharedMemorySize, FLASH_SMEM);

    // 1. prep: sincos table, x->fp16, 4 weight transposes (one launch)
    sincos_kernel<<<(S_LEN * 64) / 256, 256>>>(sc);
    const int n2x = NTOK * DMODEL / 2;
    conv_h_kernel<<<n2x / 256, 256>>>(x, xh, n2x);
    const dim3 gt(DMODEL / 32, DMODEL / 32, 4);
    transpose4_h_kernel<<<gt, 256>>>(Wq, Wk, Wv, Wo,
                                     wqh, wkh, wvh, woh, DMODEL, DMODEL);

    // 2. fused QKV projection + RoPE epilogue (256-row CTA tiles)
    const dim3 gqkv(3 * DMODEL / 128, NTOK / 256);   // (48, 16)
    hgemm1_kernel<<<gqkv, 512, G_SMEM>>>(xh, wqh, wkh, wvh,
                                         qh, kh, vh, nullptr, sc,
                                         NTOK, DMODEL, DMODEL);

    // 3. flash attention
    const dim3 gf(S_LEN / 128, NH, BATCH);           // (16, 16, 2)
    flash_mma_kernel<<<gf, 256, FLASH_SMEM>>>(qh, kh, vh, aoh);

    // 4. output projection (fp32 out)
    const dim3 go(DMODEL / 128, NTOK / 256);         // (16, 16)
    hgemm1_kernel<<<go, 512, G_SMEM>>>(aoh, woh, woh, woh,
                                       nullptr, nullptr, nullptr, out, sc,
                                       NTOK, DMODEL, DMODEL);
}

// round 11
// speedup vs baseline: 1.0505x; 1.0505x over previous
#include <cuda_runtime.h>
#include <cuda_fp16.h>
#include <math.h>
#include <stdint.h>

// Problem constants (B=2, S=2048, D=2048, H=16, HD=128)
#define S_LEN 2048
#define DMODEL 2048
#define NH 16
#define HDIM 128
#define BATCH 2
#define NTOK (BATCH * S_LEN)   // 4096

// ---------------------------------------------------------------------------
// Scratch (__device__ globals; allocation-free rule)
// ---------------------------------------------------------------------------
__device__ __half g_xh[(size_t)NTOK * DMODEL];    // x fp16
__device__ __half g_qh[(size_t)NTOK * DMODEL];    // roped Q fp16
__device__ __half g_kh[(size_t)NTOK * DMODEL];    // roped K fp16
__device__ __half g_vh[(size_t)NTOK * DMODEL];    // V fp16
__device__ __half g_aoh[(size_t)NTOK * DMODEL];   // attention out fp16
__device__ __half g_Wqh[(size_t)DMODEL * DMODEL]; // fp16, SAME layout as W [K][N]
__device__ __half g_Wkh[(size_t)DMODEL * DMODEL];
__device__ __half g_Wvh[(size_t)DMODEL * DMODEL];
__device__ __half g_Woh[(size_t)DMODEL * DMODEL];
__device__ float2 g_sc[(size_t)S_LEN * 64];       // (sin, cos) table

// ---------------------------------------------------------------------------
// Helpers
// ---------------------------------------------------------------------------
__device__ __forceinline__ uint32_t packh2(float a, float b) {
    __half2 h = __floats2half2_rn(a, b);
    return *(uint32_t*)&h;
}
__device__ __forceinline__ void mma_f16(float* c, const uint32_t* a,
                                        const uint32_t* b) {
    asm volatile(
        "mma.sync.aligned.m16n8k16.row.col.f32.f16.f16.f32 "
        "{%0,%1,%2,%3}, {%4,%5,%6,%7}, {%8,%9}, {%0,%1,%2,%3};"
        : "+f"(c[0]), "+f"(c[1]), "+f"(c[2]), "+f"(c[3])
        : "r"(a[0]), "r"(a[1]), "r"(a[2]), "r"(a[3]), "r"(b[0]), "r"(b[1]));
}
__device__ __forceinline__ uint32_t smem_u32(const void* p) {
    return (uint32_t)__cvta_generic_to_shared(p);
}
__device__ __forceinline__ void cp16(uint32_t dst, const void* src) {
    asm volatile("cp.async.cg.shared.global [%0], [%1], 16;"
                 :: "r"(dst), "l"(src));
}
__device__ __forceinline__ void cp_commit() {
    asm volatile("cp.async.commit_group;");
}
template <int N>
__device__ __forceinline__ void cp_wait() {
    asm volatile("cp.async.wait_group %0;" :: "n"(N));
}
__device__ __forceinline__ void ldsm4(uint32_t& r0, uint32_t& r1,
                                      uint32_t& r2, uint32_t& r3,
                                      uint32_t addr) {
    asm volatile("ldmatrix.sync.aligned.m8n8.x4.shared.b16 {%0,%1,%2,%3}, [%4];"
                 : "=r"(r0), "=r"(r1), "=r"(r2), "=r"(r3) : "r"(addr));
}
__device__ __forceinline__ void ldsm4t(uint32_t& r0, uint32_t& r1,
                                       uint32_t& r2, uint32_t& r3,
                                       uint32_t addr) {
    asm volatile("ldmatrix.sync.aligned.m8n8.x4.trans.shared.b16 {%0,%1,%2,%3}, [%4];"
                 : "=r"(r0), "=r"(r1), "=r"(r2), "=r"(r3) : "r"(addr));
}

// ---------------------------------------------------------------------------
// Small prep kernels
// ---------------------------------------------------------------------------
__global__ void __launch_bounds__(256) sincos_kernel(float2* __restrict__ T)
{
    const int idx = blockIdx.x * blockDim.x + threadIdx.x;   // 2048*64
    const int j = idx & 63;
    const int pos = idx >> 6;
    const double inv = exp(-(double)j * (9.210340371976184 / 64.0));
    const float ang = (float)((double)pos * inv);
    float sn, cs;
    sincosf(ang, &sn, &cs);
    T[idx] = make_float2(sn, cs);
}

__global__ void __launch_bounds__(256) conv_h_kernel(
    const float* __restrict__ X, __half* __restrict__ H, int n2)
{
    int i = blockIdx.x * blockDim.x + threadIdx.x;
    if (i >= n2) return;
    float2 v = ((const float2*)X)[i];
    ((uint32_t*)H)[i] = packh2(v.x, v.y);
}

// 4 weights, straight layout conversion fp32 -> fp16 (grid.z selects)
__global__ void __launch_bounds__(256) conv4_h_kernel(
    const float* __restrict__ W0, const float* __restrict__ W1,
    const float* __restrict__ W2, const float* __restrict__ W3,
    __half* __restrict__ T0, __half* __restrict__ T1,
    __half* __restrict__ T2, __half* __restrict__ T3, int n4)
{
    const int z = blockIdx.z;
    const float* W = (z == 0) ? W0 : (z == 1) ? W1 : (z == 2) ? W2 : W3;
    __half* Th = (z == 0) ? T0 : (z == 1) ? T1 : (z == 2) ? T2 : T3;
    int i = blockIdx.x * blockDim.x + threadIdx.x;
    if (i >= n4) return;
    float4 v = ((const float4*)W)[i];
    uint2 r;
    r.x = packh2(v.x, v.y);
    r.y = packh2(v.z, v.w);
    ((uint2*)Th)[i] = r;
}

// ---------------------------------------------------------------------------
// fp16 GEMM (R9 shape): CTA 128x128x64, 256 threads (8 warps 2m x 4n),
// warp tile 64x32, 3 cp.async stages x 32KB = 96KB -> 2 CTAs/SM.
// B is K-major [K][N] in gmem AND smem; B-frags via ldmatrix.trans
// (identical fragment values to the old transposed path).
// ONE barrier per k-tile: wait -> sync -> fill(kt+2) -> commit -> compute.
// Epilogues: Cf -> fp32; sel==2 -> fp16 (V); sel 0/1 -> fused RoPE fp16 Q/K.
// ---------------------------------------------------------------------------
#define G_STAGE 32768                 // A 16KB (128 rows x 128B) + B 16KB (64 rows x 256B)
#define G_SMEM  (3 * G_STAGE)

__global__ void __launch_bounds__(256, 2) hgemm1_kernel(
    const __half* __restrict__ Ah,
    const __half* __restrict__ B0, const __half* __restrict__ B1,
    const __half* __restrict__ B2,
    __half* __restrict__ Qout, __half* __restrict__ Kout,
    __half* __restrict__ Vout, float* __restrict__ Cf,
    const float2* __restrict__ T,
    int M, int N, int K)
{
    extern __shared__ char smem[];
    const uint32_t sbase = smem_u32(smem);

    const int tid = threadIdx.x;
    const int wid = tid >> 5;
    const int lane = tid & 31;
    const int g = lane >> 2;
    const int tig = lane & 3;
    const int warp_m = wid >> 2;        // 0..1
    const int warp_n = wid & 3;         // 0..3
    const int row0 = blockIdx.y * 128;
    const int sel = blockIdx.x >> 4;
    const int col0 = (blockIdx.x & 15) * 128;

    const __half* Bw = (sel == 0) ? B0 : (sel == 1) ? B1 : B2;   // [K][N]
    const __half* Asrc = Ah + (size_t)row0 * K;
    const __half* Bsrc = Bw + col0;

    const int ntiles = K >> 6;   // 32

    // fill k-tile kt into stage kt%3:
    //   A: 128 rows x 8 chunks (row r = m, 128B rows, swizzle ch^(r&7))
    //   B: 64 rows x 16 chunks (row r = k, 256B rows, swizzle ch^(r&7))
    auto fill = [&](int kt) {
        const uint32_t sb = sbase + (kt % 3) * G_STAGE;
        const int k0 = kt << 6;
#pragma unroll
        for (int it = 0; it < 8; ++it) {
            const int idx = tid + it * 256;          // 0..2047
            if (idx < 1024) {
                const int r = idx >> 3;              // m row 0..127
                const int ch = idx & 7;
                cp16(sb + r * 128 + ((ch ^ (r & 7)) << 4),
                     Asrc + (size_t)r * K + k0 + ch * 8);
            } else {
                const int i = idx - 1024;
                const int r = i >> 4;                // k row 0..63
                const int ch = i & 15;
                cp16(sb + 16384 + r * 256 + ((ch ^ (r & 7)) << 4),
                     Bsrc + (size_t)(k0 + r) * N + ch * 8);
            }
        }
    };

    fill(0); cp_commit();
    fill(1); cp_commit();

    float acc[4][4][4];
#pragma unroll
    for (int mf = 0; mf < 4; ++mf)
#pragma unroll
        for (int nf = 0; nf < 4; ++nf)
#pragma unroll
            for (int r = 0; r < 4; ++r) acc[mf][nf][r] = 0.0f;

    const int a_row = (lane & 7) + ((lane >> 3) & 1) * 8;
    const int a_chs = (lane >> 4) & 1;

    for (int kt = 0; kt < ntiles; ++kt) {
        cp_wait<1>();
        __syncthreads();

        if (kt + 2 < ntiles) fill(kt + 2);
        cp_commit();

        const uint32_t sA = sbase + (kt % 3) * G_STAGE;
        const uint32_t sB = sA + 16384;

#pragma unroll
        for (int ks = 0; ks < 4; ++ks) {
            // B fragments via ldmatrix.trans on K-major tile
            uint32_t bh[4][2];
            {
                const int rl = 16 * ks + (lane & 15);
#pragma unroll
                for (int nfp = 0; nfp < 2; ++nfp) {
                    const int c = warp_n * 4 + 2 * nfp + (lane >> 4);
                    uint32_t b0a, b1a, b0b, b1b;
                    ldsm4t(b0a, b1a, b0b, b1b,
                           sB + rl * 256 + ((c ^ (rl & 7)) << 4));
                    bh[2 * nfp][0] = b0a; bh[2 * nfp][1] = b1a;
                    bh[2 * nfp + 1][0] = b0b; bh[2 * nfp + 1][1] = b1b;
                }
            }
#pragma unroll
            for (int mf = 0; mf < 4; ++mf) {
                const int r = warp_m * 64 + mf * 16 + a_row;
                const int ch = 2 * ks + a_chs;
                uint32_t af[4];
                ldsm4(af[0], af[1], af[2], af[3],
                      sA + r * 128 + ((ch ^ (r & 7)) << 4));
#pragma unroll
                for (int nf = 0; nf < 4; ++nf)
                    mma_f16(acc[mf][nf], af, bh[nf]);
            }
        }
    }

    if (Cf) {
        // fp32 epilogue (output projection)
#pragma unroll
        for (int mf = 0; mf < 4; ++mf) {
            const int row = row0 + warp_m * 64 + mf * 16 + g;
#pragma unroll
            for (int nf = 0; nf < 4; ++nf) {
                const int col = col0 + warp_n * 32 + nf * 8 + 2 * tig;
                *(float2*)&Cf[(size_t)row * N + col] =
                    make_float2(acc[mf][nf][0], acc[mf][nf][1]);
                *(float2*)&Cf[(size_t)(row + 8) * N + col] =
                    make_float2(acc[mf][nf][2], acc[mf][nf][3]);
            }
        }
    } else if (sel == 2) {
        // V: fp16 plane
#pragma unroll
        for (int mf = 0; mf < 4; ++mf) {
            const int row = row0 + warp_m * 64 + mf * 16 + g;
#pragma unroll
            for (int nf = 0; nf < 4; ++nf) {
                const int col = col0 + warp_n * 32 + nf * 8 + 2 * tig;
                *(uint32_t*)&Vout[(size_t)row * N + col] =
                    packh2(acc[mf][nf][0], acc[mf][nf][1]);
                *(uint32_t*)&Vout[(size_t)(row + 8) * N + col] =
                    packh2(acc[mf][nf][2], acc[mf][nf][3]);
            }
        }
    } else {
        // Q/K: fused RoPE via smem staging (128 rows x 132 fp32 = 67.6KB)
        __syncthreads();   // all warps done with pipeline stages
        float* st = (float*)smem;
#pragma unroll
        for (int mf = 0; mf < 4; ++mf) {
            const int r1 = warp_m * 64 + mf * 16 + g;
#pragma unroll
            for (int nf = 0; nf < 4; ++nf) {
                const int c = warp_n * 32 + nf * 8 + 2 * tig;
                st[r1 * 132 + c]           = acc[mf][nf][0];
                st[r1 * 132 + c + 1]       = acc[mf][nf][1];
                st[(r1 + 8) * 132 + c]     = acc[mf][nf][2];
                st[(r1 + 8) * 132 + c + 1] = acc[mf][nf][3];
            }
        }
        __syncthreads();
        __half* Ch = (sel == 0) ? Qout : Kout;
#pragma unroll
        for (int p = 0; p < 16; ++p) {
            const int idx = tid + 256 * p;   // 0..4095
            const int r = idx >> 5;          // 0..127
            const int j = (idx & 31) * 2;    // 0..62
            const float a0 = st[r * 132 + j];
            const float a1 = st[r * 132 + j + 1];
            const float b0 = st[r * 132 + j + 64];
            const float b1 = st[r * 132 + j + 65];
            const int pos = (row0 + r) & (S_LEN - 1);
            const float2 s0 = T[pos * 64 + j];
            const float2 s1 = T[pos * 64 + j + 1];
            const float o00 = a0 * s0.y - b0 * s0.x;
            const float o10 = b0 * s0.y + a0 * s0.x;
            const float o01 = a1 * s1.y - b1 * s1.x;
            const float o11 = b1 * s1.y + a1 * s1.x;
            const size_t rb = (size_t)(row0 + r) * N + col0;
            *(uint32_t*)&Ch[rb + j]      = packh2(o00, o01);
            *(uint32_t*)&Ch[rb + j + 64] = packh2(o10, o11);
        }
    }
}

// ---------------------------------------------------------------------------
// Flash attention, fp16 single-term (causal, tanh-cap 50, sink logit 0).
// K/V double-buffered via cp.async; V row-major + ldmatrix.trans for PV.
// CTA: 128 q-rows x kv-tiles of 64; 8 warps; warp = 16 q-rows; occ 2.
// (unchanged from R9)
// ---------------------------------------------------------------------------
#define FQ 0
#define FK 8704                            // 2 x (64 rows x 68 words)
#define FV (FK + 2 * 64 * 68)              // 2 x (64 rows x 64 words)
#define FLASH_WORDS (FV + 2 * 64 * 64)     // 25600 words
#define FLASH_SMEM (FLASH_WORDS * 4)       // 102400 bytes

__global__ void __launch_bounds__(256, 2) flash_mma_kernel(
    const __half* __restrict__ Q, const __half* __restrict__ K,
    const __half* __restrict__ V, __half* __restrict__ O)
{
    extern __shared__ uint32_t sf[];
    uint32_t* Qs = sf + FQ;
    const uint32_t sbase = smem_u32(sf);

    const int qb = gridDim.x - 1 - blockIdx.x;
    const int h = blockIdx.y;
    const int b = blockIdx.z;
    const int tid = threadIdx.x;
    const int wid = tid >> 5;
    const int lane = tid & 31;
    const int g = lane >> 2;
    const int tig = lane & 3;
    const int q0 = qb * 128;

    const float SCALE = 0.08838834764831845f;
    const float CAP = 50.0f;
    const float INV_CAP = 1.0f / 50.0f;

    const size_t hb = (size_t)b * S_LEN * DMODEL + (size_t)h * HDIM;
    const __half* Qg = Q + hb;
    const __half* Kg = K + hb;
    const __half* Vg = V + hb;

    auto fillKV = [&](int kb) {
        const int k0 = kb * 64;
        const int buf = kb & 1;
        const uint32_t kb_s = sbase + (FK + buf * 64 * 68) * 4;
        const uint32_t vb_s = sbase + (FV + buf * 64 * 64) * 4;
#pragma unroll
        for (int it = 0; it < 4; ++it) {
            const int i = tid + it * 256;        // 0..1023
            const int r = i >> 4;
            const int c = i & 15;
            cp16(kb_s + r * 272 + c * 16,
                 Kg + (size_t)(k0 + r) * DMODEL + c * 8);
            cp16(vb_s + r * 256 + ((c ^ (r & 7)) << 4),
                 Vg + (size_t)(k0 + r) * DMODEL + c * 8);
        }
    };

    // Q tile fill (once)
    for (int i = tid; i < 128 * 16; i += 256) {
        const int r = i >> 4;
        const int ch = i & 15;
        *(uint4*)&Qs[r * 68 + ch * 4] =
            *(const uint4*)&Qg[(size_t)(q0 + r) * DMODEL + ch * 8];
    }

    float o[16][4];
#pragma unroll
    for (int nf = 0; nf < 16; ++nf)
#pragma unroll
        for (int r = 0; r < 4; ++r) o[nf][r] = 0.0f;

    float m0 = 0.0f, m1 = 0.0f;   // sink logit 0
    float l0 = 1.0f, l1 = 1.0f;

    const int mrow0 = wid * 16 + g;
    const int kmax = 2 * qb + 1;

    fillKV(0); cp_commit();

    for (int kb = 0; kb <= kmax; ++kb) {
        cp_wait<0>();
        __syncthreads();
        if (kb < kmax) { fillKV(kb + 1); cp_commit(); }

        const int k0 = kb * 64;
        const int buf = kb & 1;
        const uint32_t* Ks = sf + FK + buf * 64 * 68;
        const uint32_t vb_s = sbase + (FV + buf * 64 * 64) * 4;

        // S = Q K^T
        float s[8][4];
#pragma unroll
        for (int nf = 0; nf < 8; ++nf)
#pragma unroll
            for (int r = 0; r < 4; ++r) s[nf][r] = 0.0f;

#pragma unroll
        for (int ks = 0; ks < 8; ++ks) {
            const int kw = 8 * ks + tig;
            uint32_t ah[4];
            const int ra = (wid * 16 + g) * 68;
            const int rb = (wid * 16 + g + 8) * 68;
            ah[0] = Qs[ra + kw];     ah[1] = Qs[rb + kw];
            ah[2] = Qs[ra + kw + 4]; ah[3] = Qs[rb + kw + 4];
#pragma unroll
            for (int nf = 0; nf < 8; ++nf) {
                const int n = (8 * nf + g) * 68;
                uint32_t bh[2];
                bh[0] = Ks[n + kw]; bh[1] = Ks[n + kw + 4];
                mma_f16(s[nf], ah, bh);
            }
        }

        // scale, tanh-cap, causal mask
        const bool need_mask = (kb >= 2 * qb);
        const int grow0 = q0 + mrow0;
        const int grow1 = grow0 + 8;
#pragma unroll
        for (int nf = 0; nf < 8; ++nf) {
#pragma unroll
            for (int r = 0; r < 4; ++r) {
                float v = s[nf][r] * SCALE;
                v = CAP * tanhf(v * INV_CAP);
                if (need_mask) {
                    const int col = k0 + 8 * nf + 2 * tig + (r & 1);
                    const int row = (r < 2) ? grow0 : grow1;
                    if (col > row) v = -INFINITY;
                }
                s[nf][r] = v;
            }
        }

        // online softmax
        float rmax0 = -3.4e38f, rmax1 = -3.4e38f;
#pragma unroll
        for (int nf = 0; nf < 8; ++nf) {
            rmax0 = fmaxf(rmax0, fmaxf(s[nf][0], s[nf][1]));
            rmax1 = fmaxf(rmax1, fmaxf(s[nf][2], s[nf][3]));
        }
#pragma unroll
        for (int w = 1; w < 4; w <<= 1) {
            rmax0 = fmaxf(rmax0, __shfl_xor_sync(0xffffffffu, rmax0, w));
            rmax1 = fmaxf(rmax1, __shfl_xor_sync(0xffffffffu, rmax1, w));
        }
        const float mn0 = fmaxf(m0, rmax0);
        const float mn1 = fmaxf(m1, rmax1);
        const float cr0 = __expf(m0 - mn0);
        const float cr1 = __expf(m1 - mn1);
        m0 = mn0; m1 = mn1;

        float rs0 = 0.0f, rs1 = 0.0f;
#pragma unroll
        for (int nf = 0; nf < 8; ++nf) {
            s[nf][0] = __expf(s[nf][0] - mn0);
            s[nf][1] = __expf(s[nf][1] - mn0);
            s[nf][2] = __expf(s[nf][2] - mn1);
            s[nf][3] = __expf(s[nf][3] - mn1);
            rs0 += s[nf][0] + s[nf][1];
            rs1 += s[nf][2] + s[nf][3];
        }
#pragma unroll
        for (int w = 1; w < 4; w <<= 1) {
            rs0 += __shfl_xor_sync(0xffffffffu, rs0, w);
            rs1 += __shfl_xor_sync(0xffffffffu, rs1, w);
        }
        l0 = l0 * cr0 + rs0;
        l1 = l1 * cr1 + rs1;

#pragma unroll
        for (int nf = 0; nf < 16; ++nf) {
            o[nf][0] *= cr0; o[nf][1] *= cr0;
            o[nf][2] *= cr1; o[nf][3] *= cr1;
        }

        // O += P V : P rounded fp16; V fragments via ldmatrix.trans
#pragma unroll
        for (int ks = 0; ks < 4; ++ks) {
            uint32_t ah[4];
            ah[0] = packh2(s[2 * ks][0],     s[2 * ks][1]);
            ah[1] = packh2(s[2 * ks][2],     s[2 * ks][3]);
            ah[2] = packh2(s[2 * ks + 1][0], s[2 * ks + 1][1]);
            ah[3] = packh2(s[2 * ks + 1][2], s[2 * ks + 1][3]);
            const int rl = 16 * ks + (lane & 15);
#pragma unroll
            for (int nfp = 0; nfp < 8; ++nfp) {
                const int c = 2 * nfp + (lane >> 4);
                uint32_t b0a, b1a, b0b, b1b;
                ldsm4t(b0a, b1a, b0b, b1b,
                       vb_s + rl * 256 + ((c ^ (rl & 7)) << 4));
                uint32_t bA[2] = { b0a, b1a };
                uint32_t bB[2] = { b0b, b1b };
                mma_f16(o[2 * nfp],     ah, bA);
                mma_f16(o[2 * nfp + 1], ah, bB);
            }
        }
    }

    // epilogue: normalize + write fp16 AO plane
    const float inv0 = 1.0f / l0;
    const float inv1 = 1.0f / l1;
    __half* Og = O + hb;
    const int row0g = q0 + wid * 16 + g;
#pragma unroll
    for (int nf = 0; nf < 16; ++nf) {
        const int col = 8 * nf + 2 * tig;
        *(uint32_t*)&Og[(size_t)row0g * DMODEL + col] =
            packh2(o[nf][0] * inv0, o[nf][1] * inv0);
        *(uint32_t*)&Og[(size_t)(row0g + 8) * DMODEL + col] =
            packh2(o[nf][2] * inv1, o[nf][3] * inv1);
    }
}

// ---------------------------------------------------------------------------
extern "C" void kernel_launch(void* const* d_in, const int* in_sizes, int n_in,
                              void* d_out, int out_size)
{
    const float* x  = (const float*)d_in[0];
    const float* Wq = (const float*)d_in[1];
    const float* Wk = (const float*)d_in[2];
    const float* Wv = (const float*)d_in[3];
    const float* Wo = (const float*)d_in[4];
    float* out = (float*)d_out;

    __half *xh, *qh, *kh, *vh, *aoh, *wqh, *wkh, *wvh, *woh;
    float2* sc;
    cudaGetSymbolAddress((void**)&xh,  g_xh);
    cudaGetSymbolAddress((void**)&qh,  g_qh);
    cudaGetSymbolAddress((void**)&kh,  g_kh);
    cudaGetSymbolAddress((void**)&vh,  g_vh);
    cudaGetSymbolAddress((void**)&aoh, g_aoh);
    cudaGetSymbolAddress((void**)&wqh, g_Wqh);
    cudaGetSymbolAddress((void**)&wkh, g_Wkh);
    cudaGetSymbolAddress((void**)&wvh, g_Wvh);
    cudaGetSymbolAddress((void**)&woh, g_Woh);
    cudaGetSymbolAddress((void**)&sc,  g_sc);

    cudaFuncSetAttribute(hgemm1_kernel,
                         cudaFuncAttributeMaxDynamicSharedMemorySize, G_SMEM);
    cudaFuncSetAttribute(flash_mma_kernel,
                         cudaFuncAttributeMaxDynamicSharedMemorySize, FLASH_SMEM);

    // 1. prep: sincos table, x->fp16, 4 weight converts (one launch, no transpose)
    sincos_kernel<<<(S_LEN * 64) / 256, 256>>>(sc);
    const int n2x = NTOK * DMODEL / 2;
    conv_h_kernel<<<n2x / 256, 256>>>(x, xh, n2x);
    const int n4w = DMODEL * DMODEL / 4;
    const dim3 gw(n4w / 256, 1, 4);
    conv4_h_kernel<<<gw, 256>>>(Wq, Wk, Wv, Wo,
                                wqh, wkh, wvh, woh, n4w);

    // 2. fused QKV projection + RoPE epilogue
    const dim3 gqkv(3 * DMODEL / 128, NTOK / 128);   // (48, 32)
    hgemm1_kernel<<<gqkv, 256, G_SMEM>>>(xh, wqh, wkh, wvh,
                                         qh, kh, vh, nullptr, sc,
                                         NTOK, DMODEL, DMODEL);

    // 3. flash attention
    const dim3 gf(S_LEN / 128, NH, BATCH);           // (16, 16, 2)
    flash_mma_kernel<<<gf, 256, FLASH_SMEM>>>(qh, kh, vh, aoh);

    // 4. output projection (fp32 out)
    const dim3 go(DMODEL / 128, NTOK / 128);         // (16, 32)
    hgemm1_kernel<<<go, 256, G_SMEM>>>(aoh, woh, woh, woh,
                                       nullptr, nullptr, nullptr, out, sc,
                                       NTOK, DMODEL, DMODEL);
}

// round 12
// speedup vs baseline: 1.0790x; 1.0271x over previous
#include <cuda_runtime.h>
#include <cuda_fp16.h>
#include <math.h>
#include <stdint.h>

// Problem constants (B=2, S=2048, D=2048, H=16, HD=128)
#define S_LEN 2048
#define DMODEL 2048
#define NH 16
#define HDIM 128
#define BATCH 2
#define NTOK (BATCH * S_LEN)   // 4096

// ---------------------------------------------------------------------------
// Scratch (__device__ globals; allocation-free rule)
// ---------------------------------------------------------------------------
__device__ __half g_xh[(size_t)NTOK * DMODEL];    // x fp16
__device__ __half g_qh[(size_t)NTOK * DMODEL];    // roped Q fp16 (pre-scaled by 1/sqrt(hd))
__device__ __half g_kh[(size_t)NTOK * DMODEL];    // roped K fp16
__device__ __half g_vh[(size_t)NTOK * DMODEL];    // V fp16
__device__ __half g_aoh[(size_t)NTOK * DMODEL];   // attention out fp16
__device__ __half g_Wqh[(size_t)DMODEL * DMODEL]; // fp16, SAME layout as W [K][N]
__device__ __half g_Wkh[(size_t)DMODEL * DMODEL];
__device__ __half g_Wvh[(size_t)DMODEL * DMODEL];
__device__ __half g_Woh[(size_t)DMODEL * DMODEL];
__device__ float2 g_sc[(size_t)S_LEN * 64];       // (sin, cos) table

// ---------------------------------------------------------------------------
// Helpers
// ---------------------------------------------------------------------------
__device__ __forceinline__ uint32_t packh2(float a, float b) {
    __half2 h = __floats2half2_rn(a, b);
    return *(uint32_t*)&h;
}
__device__ __forceinline__ void mma_f16(float* c, const uint32_t* a,
                                        const uint32_t* b) {
    asm volatile(
        "mma.sync.aligned.m16n8k16.row.col.f32.f16.f16.f32 "
        "{%0,%1,%2,%3}, {%4,%5,%6,%7}, {%8,%9}, {%0,%1,%2,%3};"
        : "+f"(c[0]), "+f"(c[1]), "+f"(c[2]), "+f"(c[3])
        : "r"(a[0]), "r"(a[1]), "r"(a[2]), "r"(a[3]), "r"(b[0]), "r"(b[1]));
}
__device__ __forceinline__ uint32_t smem_u32(const void* p) {
    return (uint32_t)__cvta_generic_to_shared(p);
}
__device__ __forceinline__ void cp16(uint32_t dst, const void* src) {
    asm volatile("cp.async.cg.shared.global [%0], [%1], 16;"
                 :: "r"(dst), "l"(src));
}
__device__ __forceinline__ void cp_commit() {
    asm volatile("cp.async.commit_group;");
}
template <int N>
__device__ __forceinline__ void cp_wait() {
    asm volatile("cp.async.wait_group %0;" :: "n"(N));
}
__device__ __forceinline__ void ldsm4(uint32_t& r0, uint32_t& r1,
                                      uint32_t& r2, uint32_t& r3,
                                      uint32_t addr) {
    asm volatile("ldmatrix.sync.aligned.m8n8.x4.shared.b16 {%0,%1,%2,%3}, [%4];"
                 : "=r"(r0), "=r"(r1), "=r"(r2), "=r"(r3) : "r"(addr));
}
__device__ __forceinline__ void ldsm4t(uint32_t& r0, uint32_t& r1,
                                       uint32_t& r2, uint32_t& r3,
                                       uint32_t addr) {
    asm volatile("ldmatrix.sync.aligned.m8n8.x4.trans.shared.b16 {%0,%1,%2,%3}, [%4];"
                 : "=r"(r0), "=r"(r1), "=r"(r2), "=r"(r3) : "r"(addr));
}
// CAP*tanh(v/CAP) via exp identity: 50 - 100/(exp(v*0.04)+1)
__device__ __forceinline__ float captanh(float v) {
    const float e = __expf(v * 0.04f);
    return 50.0f - __fdividef(100.0f, e + 1.0f);
}

// ---------------------------------------------------------------------------
// Small prep kernels
// ---------------------------------------------------------------------------
__global__ void __launch_bounds__(256) sincos_kernel(float2* __restrict__ T)
{
    const int idx = blockIdx.x * blockDim.x + threadIdx.x;   // 2048*64
    const int j = idx & 63;
    const int pos = idx >> 6;
    const double inv = exp(-(double)j * (9.210340371976184 / 64.0));
    const float ang = (float)((double)pos * inv);
    float sn, cs;
    sincosf(ang, &sn, &cs);
    T[idx] = make_float2(sn, cs);
}

__global__ void __launch_bounds__(256) conv_h_kernel(
    const float* __restrict__ X, __half* __restrict__ H, int n2)
{
    int i = blockIdx.x * blockDim.x + threadIdx.x;
    if (i >= n2) return;
    float2 v = ((const float2*)X)[i];
    ((uint32_t*)H)[i] = packh2(v.x, v.y);
}

// 4 weights, straight layout conversion fp32 -> fp16 (grid.z selects)
__global__ void __launch_bounds__(256) conv4_h_kernel(
    const float* __restrict__ W0, const float* __restrict__ W1,
    const float* __restrict__ W2, const float* __restrict__ W3,
    __half* __restrict__ T0, __half* __restrict__ T1,
    __half* __restrict__ T2, __half* __restrict__ T3, int n4)
{
    const int z = blockIdx.z;
    const float* W = (z == 0) ? W0 : (z == 1) ? W1 : (z == 2) ? W2 : W3;
    __half* Th = (z == 0) ? T0 : (z == 1) ? T1 : (z == 2) ? T2 : T3;
    int i = blockIdx.x * blockDim.x + threadIdx.x;
    if (i >= n4) return;
    float4 v = ((const float4*)W)[i];
    uint2 r;
    r.x = packh2(v.x, v.y);
    r.y = packh2(v.z, v.w);
    ((uint2*)Th)[i] = r;
}

// ---------------------------------------------------------------------------
// fp16 GEMM: CTA 128x128x64, 256 threads (8 warps 2m x 4n), warp 64x32,
// 3 cp.async stages x 32KB = 96KB -> 2 CTAs/SM. B K-major, frags via
// ldmatrix.trans. One barrier per k-tile.
// Epilogues: Cf -> fp32; sel==2 -> fp16 (V); sel 0/1 -> fused RoPE fp16
// (Q additionally pre-scaled by 1/sqrt(HD)).
// ---------------------------------------------------------------------------
#define G_STAGE 32768
#define G_SMEM  (3 * G_STAGE)

__global__ void __launch_bounds__(256, 2) hgemm1_kernel(
    const __half* __restrict__ Ah,
    const __half* __restrict__ B0, const __half* __restrict__ B1,
    const __half* __restrict__ B2,
    __half* __restrict__ Qout, __half* __restrict__ Kout,
    __half* __restrict__ Vout, float* __restrict__ Cf,
    const float2* __restrict__ T,
    int M, int N, int K)
{
    extern __shared__ char smem[];
    const uint32_t sbase = smem_u32(smem);

    const int tid = threadIdx.x;
    const int wid = tid >> 5;
    const int lane = tid & 31;
    const int g = lane >> 2;
    const int tig = lane & 3;
    const int warp_m = wid >> 2;
    const int warp_n = wid & 3;
    const int row0 = blockIdx.y * 128;
    const int sel = blockIdx.x >> 4;
    const int col0 = (blockIdx.x & 15) * 128;

    const __half* Bw = (sel == 0) ? B0 : (sel == 1) ? B1 : B2;   // [K][N]
    const __half* Asrc = Ah + (size_t)row0 * K;
    const __half* Bsrc = Bw + col0;

    const int ntiles = K >> 6;   // 32

    auto fill = [&](int kt) {
        const uint32_t sb = sbase + (kt % 3) * G_STAGE;
        const int k0 = kt << 6;
#pragma unroll
        for (int it = 0; it < 8; ++it) {
            const int idx = tid + it * 256;          // 0..2047
            if (idx < 1024) {
                const int r = idx >> 3;              // m row 0..127
                const int ch = idx & 7;
                cp16(sb + r * 128 + ((ch ^ (r & 7)) << 4),
                     Asrc + (size_t)r * K + k0 + ch * 8);
            } else {
                const int i = idx - 1024;
                const int r = i >> 4;                // k row 0..63
                const int ch = i & 15;
                cp16(sb + 16384 + r * 256 + ((ch ^ (r & 7)) << 4),
                     Bsrc + (size_t)(k0 + r) * N + ch * 8);
            }
        }
    };

    fill(0); cp_commit();
    fill(1); cp_commit();

    float acc[4][4][4];
#pragma unroll
    for (int mf = 0; mf < 4; ++mf)
#pragma unroll
        for (int nf = 0; nf < 4; ++nf)
#pragma unroll
            for (int r = 0; r < 4; ++r) acc[mf][nf][r] = 0.0f;

    const int a_row = (lane & 7) + ((lane >> 3) & 1) * 8;
    const int a_chs = (lane >> 4) & 1;

    for (int kt = 0; kt < ntiles; ++kt) {
        cp_wait<1>();
        __syncthreads();

        if (kt + 2 < ntiles) fill(kt + 2);
        cp_commit();

        const uint32_t sA = sbase + (kt % 3) * G_STAGE;
        const uint32_t sB = sA + 16384;

#pragma unroll
        for (int ks = 0; ks < 4; ++ks) {
            uint32_t bh[4][2];
            {
                const int rl = 16 * ks + (lane & 15);
#pragma unroll
                for (int nfp = 0; nfp < 2; ++nfp) {
                    const int c = warp_n * 4 + 2 * nfp + (lane >> 4);
                    uint32_t b0a, b1a, b0b, b1b;
                    ldsm4t(b0a, b1a, b0b, b1b,
                           sB + rl * 256 + ((c ^ (rl & 7)) << 4));
                    bh[2 * nfp][0] = b0a; bh[2 * nfp][1] = b1a;
                    bh[2 * nfp + 1][0] = b0b; bh[2 * nfp + 1][1] = b1b;
                }
            }
#pragma unroll
            for (int mf = 0; mf < 4; ++mf) {
                const int r = warp_m * 64 + mf * 16 + a_row;
                const int ch = 2 * ks + a_chs;
                uint32_t af[4];
                ldsm4(af[0], af[1], af[2], af[3],
                      sA + r * 128 + ((ch ^ (r & 7)) << 4));
#pragma unroll
                for (int nf = 0; nf < 4; ++nf)
                    mma_f16(acc[mf][nf], af, bh[nf]);
            }
        }
    }

    if (Cf) {
#pragma unroll
        for (int mf = 0; mf < 4; ++mf) {
            const int row = row0 + warp_m * 64 + mf * 16 + g;
#pragma unroll
            for (int nf = 0; nf < 4; ++nf) {
                const int col = col0 + warp_n * 32 + nf * 8 + 2 * tig;
                *(float2*)&Cf[(size_t)row * N + col] =
                    make_float2(acc[mf][nf][0], acc[mf][nf][1]);
                *(float2*)&Cf[(size_t)(row + 8) * N + col] =
                    make_float2(acc[mf][nf][2], acc[mf][nf][3]);
            }
        }
    } else if (sel == 2) {
#pragma unroll
        for (int mf = 0; mf < 4; ++mf) {
            const int row = row0 + warp_m * 64 + mf * 16 + g;
#pragma unroll
            for (int nf = 0; nf < 4; ++nf) {
                const int col = col0 + warp_n * 32 + nf * 8 + 2 * tig;
                *(uint32_t*)&Vout[(size_t)row * N + col] =
                    packh2(acc[mf][nf][0], acc[mf][nf][1]);
                *(uint32_t*)&Vout[(size_t)(row + 8) * N + col] =
                    packh2(acc[mf][nf][2], acc[mf][nf][3]);
            }
        }
    } else {
        // Q/K: fused RoPE via smem staging; Q pre-scaled by 1/sqrt(HD)
        __syncthreads();
        float* st = (float*)smem;
#pragma unroll
        for (int mf = 0; mf < 4; ++mf) {
            const int r1 = warp_m * 64 + mf * 16 + g;
#pragma unroll
            for (int nf = 0; nf < 4; ++nf) {
                const int c = warp_n * 32 + nf * 8 + 2 * tig;
                st[r1 * 132 + c]           = acc[mf][nf][0];
                st[r1 * 132 + c + 1]       = acc[mf][nf][1];
                st[(r1 + 8) * 132 + c]     = acc[mf][nf][2];
                st[(r1 + 8) * 132 + c + 1] = acc[mf][nf][3];
            }
        }
        __syncthreads();
        __half* Ch = (sel == 0) ? Qout : Kout;
        const float post = (sel == 0) ? 0.08838834764831845f : 1.0f;
#pragma unroll
        for (int p = 0; p < 16; ++p) {
            const int idx = tid + 256 * p;   // 0..4095
            const int r = idx >> 5;          // 0..127
            const int j = (idx & 31) * 2;    // 0..62
            const float a0 = st[r * 132 + j];
            const float a1 = st[r * 132 + j + 1];
            const float b0 = st[r * 132 + j + 64];
            const float b1 = st[r * 132 + j + 65];
            const int pos = (row0 + r) & (S_LEN - 1);
            const float2 s0 = T[pos * 64 + j];
            const float2 s1 = T[pos * 64 + j + 1];
            const float o00 = (a0 * s0.y - b0 * s0.x) * post;
            const float o10 = (b0 * s0.y + a0 * s0.x) * post;
            const float o01 = (a1 * s1.y - b1 * s1.x) * post;
            const float o11 = (b1 * s1.y + a1 * s1.x) * post;
            const size_t rb = (size_t)(row0 + r) * N + col0;
            *(uint32_t*)&Ch[rb + j]      = packh2(o00, o01);
            *(uint32_t*)&Ch[rb + j + 64] = packh2(o10, o11);
        }
    }
}

// ---------------------------------------------------------------------------
// Flash attention, fp16 single-term (causal, tanh-cap 50, sink logit 0).
// Q pre-scaled; captanh via exp identity (no tanhf).
// K/V double-buffered via cp.async; V row-major + ldmatrix.trans for PV.
// CTA: 128 q-rows x kv-tiles of 64; 8 warps; warp = 16 q-rows; occ 2.
// ---------------------------------------------------------------------------
#define FQ 0
#define FK 8704                            // 2 x (64 rows x 68 words)
#define FV (FK + 2 * 64 * 68)              // 2 x (64 rows x 64 words)
#define FLASH_WORDS (FV + 2 * 64 * 64)     // 25600 words
#define FLASH_SMEM (FLASH_WORDS * 4)       // 102400 bytes

__global__ void __launch_bounds__(256, 2) flash_mma_kernel(
    const __half* __restrict__ Q, const __half* __restrict__ K,
    const __half* __restrict__ V, __half* __restrict__ O)
{
    extern __shared__ uint32_t sf[];
    uint32_t* Qs = sf + FQ;
    const uint32_t sbase = smem_u32(sf);

    const int qb = gridDim.x - 1 - blockIdx.x;
    const int h = blockIdx.y;
    const int b = blockIdx.z;
    const int tid = threadIdx.x;
    const int wid = tid >> 5;
    const int lane = tid & 31;
    const int g = lane >> 2;
    const int tig = lane & 3;
    const int q0 = qb * 128;

    const size_t hb = (size_t)b * S_LEN * DMODEL + (size_t)h * HDIM;
    const __half* Qg = Q + hb;
    const __half* Kg = K + hb;
    const __half* Vg = V + hb;

    auto fillKV = [&](int kb) {
        const int k0 = kb * 64;
        const int buf = kb & 1;
        const uint32_t kb_s = sbase + (FK + buf * 64 * 68) * 4;
        const uint32_t vb_s = sbase + (FV + buf * 64 * 64) * 4;
#pragma unroll
        for (int it = 0; it < 4; ++it) {
            const int i = tid + it * 256;        // 0..1023
            const int r = i >> 4;
            const int c = i & 15;
            cp16(kb_s + r * 272 + c * 16,
                 Kg + (size_t)(k0 + r) * DMODEL + c * 8);
            cp16(vb_s + r * 256 + ((c ^ (r & 7)) << 4),
                 Vg + (size_t)(k0 + r) * DMODEL + c * 8);
        }
    };

    // Q tile fill (once)
    for (int i = tid; i < 128 * 16; i += 256) {
        const int r = i >> 4;
        const int ch = i & 15;
        *(uint4*)&Qs[r * 68 + ch * 4] =
            *(const uint4*)&Qg[(size_t)(q0 + r) * DMODEL + ch * 8];
    }

    float o[16][4];
#pragma unroll
    for (int nf = 0; nf < 16; ++nf)
#pragma unroll
        for (int r = 0; r < 4; ++r) o[nf][r] = 0.0f;

    float m0 = 0.0f, m1 = 0.0f;   // sink logit 0
    float l0 = 1.0f, l1 = 1.0f;

    const int mrow0 = wid * 16 + g;
    const int kmax = 2 * qb + 1;

    fillKV(0); cp_commit();

    for (int kb = 0; kb <= kmax; ++kb) {
        cp_wait<0>();
        __syncthreads();
        if (kb < kmax) { fillKV(kb + 1); cp_commit(); }

        const int k0 = kb * 64;
        const int buf = kb & 1;
        const uint32_t* Ks = sf + FK + buf * 64 * 68;
        const uint32_t vb_s = sbase + (FV + buf * 64 * 64) * 4;

        // S = Q K^T (Q pre-scaled)
        float s[8][4];
#pragma unroll
        for (int nf = 0; nf < 8; ++nf)
#pragma unroll
            for (int r = 0; r < 4; ++r) s[nf][r] = 0.0f;

#pragma unroll
        for (int ks = 0; ks < 8; ++ks) {
            const int kw = 8 * ks + tig;
            uint32_t ah[4];
            const int ra = (wid * 16 + g) * 68;
            const int rb = (wid * 16 + g + 8) * 68;
            ah[0] = Qs[ra + kw];     ah[1] = Qs[rb + kw];
            ah[2] = Qs[ra + kw + 4]; ah[3] = Qs[rb + kw + 4];
#pragma unroll
            for (int nf = 0; nf < 8; ++nf) {
                const int n = (8 * nf + g) * 68;
                uint32_t bh[2];
                bh[0] = Ks[n + kw]; bh[1] = Ks[n + kw + 4];
                mma_f16(s[nf], ah, bh);
            }
        }

        // tanh-cap (exp identity) + causal mask
        const bool need_mask = (kb >= 2 * qb);
        const int grow0 = q0 + mrow0;
        const int grow1 = grow0 + 8;
#pragma unroll
        for (int nf = 0; nf < 8; ++nf) {
#pragma unroll
            for (int r = 0; r < 4; ++r) {
                float v = captanh(s[nf][r]);
                if (need_mask) {
                    const int col = k0 + 8 * nf + 2 * tig + (r & 1);
                    const int row = (r < 2) ? grow0 : grow1;
                    if (col > row) v = -INFINITY;
                }
                s[nf][r] = v;
            }
        }

        // online softmax
        float rmax0 = -3.4e38f, rmax1 = -3.4e38f;
#pragma unroll
        for (int nf = 0; nf < 8; ++nf) {
            rmax0 = fmaxf(rmax0, fmaxf(s[nf][0], s[nf][1]));
            rmax1 = fmaxf(rmax1, fmaxf(s[nf][2], s[nf][3]));
        }
#pragma unroll
        for (int w = 1; w < 4; w <<= 1) {
            rmax0 = fmaxf(rmax0, __shfl_xor_sync(0xffffffffu, rmax0, w));
            rmax1 = fmaxf(rmax1, __shfl_xor_sync(0xffffffffu, rmax1, w));
        }
        const float mn0 = fmaxf(m0, rmax0);
        const float mn1 = fmaxf(m1, rmax1);
        const float cr0 = __expf(m0 - mn0);
        const float cr1 = __expf(m1 - mn1);
        m0 = mn0; m1 = mn1;

        float rs0 = 0.0f, rs1 = 0.0f;
#pragma unroll
        for (int nf = 0; nf < 8; ++nf) {
            s[nf][0] = __expf(s[nf][0] - mn0);
            s[nf][1] = __expf(s[nf][1] - mn0);
            s[nf][2] = __expf(s[nf][2] - mn1);
            s[nf][3] = __expf(s[nf][3] - mn1);
            rs0 += s[nf][0] + s[nf][1];
            rs1 += s[nf][2] + s[nf][3];
        }
#pragma unroll
        for (int w = 1; w < 4; w <<= 1) {
            rs0 += __shfl_xor_sync(0xffffffffu, rs0, w);
            rs1 += __shfl_xor_sync(0xffffffffu, rs1, w);
        }
        l0 = l0 * cr0 + rs0;
        l1 = l1 * cr1 + rs1;

#pragma unroll
        for (int nf = 0; nf < 16; ++nf) {
            o[nf][0] *= cr0; o[nf][1] *= cr0;
            o[nf][2] *= cr1; o[nf][3] *= cr1;
        }

        // O += P V : P rounded fp16; V fragments via ldmatrix.trans
#pragma unroll
        for (int ks = 0; ks < 4; ++ks) {
            uint32_t ah[4];
            ah[0] = packh2(s[2 * ks][0],     s[2 * ks][1]);
            ah[1] = packh2(s[2 * ks][2],     s[2 * ks][3]);
            ah[2] = packh2(s[2 * ks + 1][0], s[2 * ks + 1][1]);
            ah[3] = packh2(s[2 * ks + 1][2], s[2 * ks + 1][3]);
            const int rl = 16 * ks + (lane & 15);
#pragma unroll
            for (int nfp = 0; nfp < 8; ++nfp) {
                const int c = 2 * nfp + (lane >> 4);
                uint32_t b0a, b1a, b0b, b1b;
                ldsm4t(b0a, b1a, b0b, b1b,
                       vb_s + rl * 256 + ((c ^ (rl & 7)) << 4));
                uint32_t bA[2] = { b0a, b1a };
                uint32_t bB[2] = { b0b, b1b };
                mma_f16(o[2 * nfp],     ah, bA);
                mma_f16(o[2 * nfp + 1], ah, bB);
            }
        }
    }

    // epilogue: normalize + write fp16 AO plane
    const float inv0 = 1.0f / l0;
    const float inv1 = 1.0f / l1;
    __half* Og = O + hb;
    const int row0g = q0 + wid * 16 + g;
#pragma unroll
    for (int nf = 0; nf < 16; ++nf) {
        const int col = 8 * nf + 2 * tig;
        *(uint32_t*)&Og[(size_t)row0g * DMODEL + col] =
            packh2(o[nf][0] * inv0, o[nf][1] * inv0);
        *(uint32_t*)&Og[(size_t)(row0g + 8) * DMODEL + col] =
            packh2(o[nf][2] * inv1, o[nf][3] * inv1);
    }
}

// ---------------------------------------------------------------------------
extern "C" void kernel_launch(void* const* d_in, const int* in_sizes, int n_in,
                              void* d_out, int out_size)
{
    const float* x  = (const float*)d_in[0];
    const float* Wq = (const float*)d_in[1];
    const float* Wk = (const float*)d_in[2];
    const float* Wv = (const float*)d_in[3];
    const float* Wo = (const float*)d_in[4];
    float* out = (float*)d_out;

    __half *xh, *qh, *kh, *vh, *aoh, *wqh, *wkh, *wvh, *woh;
    float2* sc;
    cudaGetSymbolAddress((void**)&xh,  g_xh);
    cudaGetSymbolAddress((void**)&qh,  g_qh);
    cudaGetSymbolAddress((void**)&kh,  g_kh);
    cudaGetSymbolAddress((void**)&vh,  g_vh);
    cudaGetSymbolAddress((void**)&aoh, g_aoh);
    cudaGetSymbolAddress((void**)&wqh, g_Wqh);
    cudaGetSymbolAddress((void**)&wkh, g_Wkh);
    cudaGetSymbolAddress((void**)&wvh, g_Wvh);
    cudaGetSymbolAddress((void**)&woh, g_Woh);
    cudaGetSymbolAddress((void**)&sc,  g_sc);

    cudaFuncSetAttribute(hgemm1_kernel,
                         cudaFuncAttributeMaxDynamicSharedMemorySize, G_SMEM);
    cudaFuncSetAttribute(flash_mma_kernel,
                         cudaFuncAttributeMaxDynamicSharedMemorySize, FLASH_SMEM);

    // 1. prep
    sincos_kernel<<<(S_LEN * 64) / 256, 256>>>(sc);
    const int n2x = NTOK * DMODEL / 2;
    conv_h_kernel<<<n2x / 256, 256>>>(x, xh, n2x);
    const int n4w = DMODEL * DMODEL / 4;
    const dim3 gw(n4w / 256, 1, 4);
    conv4_h_kernel<<<gw, 256>>>(Wq, Wk, Wv, Wo,
                                wqh, wkh, wvh, woh, n4w);

    // 2. fused QKV projection + RoPE epilogue (Q pre-scaled)
    const dim3 gqkv(3 * DMODEL / 128, NTOK / 128);   // (48, 32)
    hgemm1_kernel<<<gqkv, 256, G_SMEM>>>(xh, wqh, wkh, wvh,
                                         qh, kh, vh, nullptr, sc,
                                         NTOK, DMODEL, DMODEL);

    // 3. flash attention
    const dim3 gf(S_LEN / 128, NH, BATCH);           // (16, 16, 2)
    flash_mma_kernel<<<gf, 256, FLASH_SMEM>>>(qh, kh, vh, aoh);

    // 4. output projection (fp32 out)
    const dim3 go(DMODEL / 128, NTOK / 128);         // (16, 32)
    hgemm1_kernel<<<go, 256, G_SMEM>>>(aoh, woh, woh, woh,
                                       nullptr, nullptr, nullptr, out, sc,
                                       NTOK, DMODEL, DMODEL);
}

// round 13
// speedup vs baseline: 1.1547x; 1.0702x over previous
#include <cuda_runtime.h>
#include <cuda_fp16.h>
#include <math.h>
#include <stdint.h>

// Problem constants (B=2, S=2048, D=2048, H=16, HD=128)
#define S_LEN 2048
#define DMODEL 2048
#define NH 16
#define HDIM 128
#define BATCH 2
#define NTOK (BATCH * S_LEN)   // 4096

// ---------------------------------------------------------------------------
// Scratch (__device__ globals; allocation-free rule)
// ---------------------------------------------------------------------------
__device__ __half g_xh[(size_t)NTOK * DMODEL];
__device__ __half g_qh[(size_t)NTOK * DMODEL];    // roped Q fp16 (pre-scaled)
__device__ __half g_kh[(size_t)NTOK * DMODEL];
__device__ __half g_vh[(size_t)NTOK * DMODEL];
__device__ __half g_aoh[(size_t)NTOK * DMODEL];
__device__ __half g_Wqh[(size_t)DMODEL * DMODEL]; // fp16, layout [K][N]
__device__ __half g_Wkh[(size_t)DMODEL * DMODEL];
__device__ __half g_Wvh[(size_t)DMODEL * DMODEL];
__device__ __half g_Woh[(size_t)DMODEL * DMODEL];
__device__ float2 g_sc[(size_t)S_LEN * 64];

// ---------------------------------------------------------------------------
// Helpers
// ---------------------------------------------------------------------------
__device__ __forceinline__ uint32_t packh2(float a, float b) {
    __half2 h = __floats2half2_rn(a, b);
    return *(uint32_t*)&h;
}
__device__ __forceinline__ void mma_f16(float* c, const uint32_t* a,
                                        const uint32_t* b) {
    asm volatile(
        "mma.sync.aligned.m16n8k16.row.col.f32.f16.f16.f32 "
        "{%0,%1,%2,%3}, {%4,%5,%6,%7}, {%8,%9}, {%0,%1,%2,%3};"
        : "+f"(c[0]), "+f"(c[1]), "+f"(c[2]), "+f"(c[3])
        : "r"(a[0]), "r"(a[1]), "r"(a[2]), "r"(a[3]), "r"(b[0]), "r"(b[1]));
}
__device__ __forceinline__ uint32_t smem_u32(const void* p) {
    return (uint32_t)__cvta_generic_to_shared(p);
}
__device__ __forceinline__ void cp16(uint32_t dst, const void* src) {
    asm volatile("cp.async.cg.shared.global [%0], [%1], 16;"
                 :: "r"(dst), "l"(src));
}
__device__ __forceinline__ void cp_commit() {
    asm volatile("cp.async.commit_group;");
}
template <int N>
__device__ __forceinline__ void cp_wait() {
    asm volatile("cp.async.wait_group %0;" :: "n"(N));
}
__device__ __forceinline__ void ldsm4(uint32_t& r0, uint32_t& r1,
                                      uint32_t& r2, uint32_t& r3,
                                      uint32_t addr) {
    asm volatile("ldmatrix.sync.aligned.m8n8.x4.shared.b16 {%0,%1,%2,%3}, [%4];"
                 : "=r"(r0), "=r"(r1), "=r"(r2), "=r"(r3) : "r"(addr));
}
__device__ __forceinline__ void ldsm4t(uint32_t& r0, uint32_t& r1,
                                       uint32_t& r2, uint32_t& r3,
                                       uint32_t addr) {
    asm volatile("ldmatrix.sync.aligned.m8n8.x4.trans.shared.b16 {%0,%1,%2,%3}, [%4];"
                 : "=r"(r0), "=r"(r1), "=r"(r2), "=r"(r3) : "r"(addr));
}
// CAP*tanh(v/CAP) = 50 - 100/(exp(0.04v)+1)
__device__ __forceinline__ float captanh(float v) {
    const float e = __expf(v * 0.04f);
    return 50.0f - __fdividef(100.0f, e + 1.0f);
}

// ---------------------------------------------------------------------------
// Fused prep: sincos table + x->fp16 + 4 weight converts, one launch.
// Grid layout: [0,512) sincos | [512,8704) x | [8704,25088) weights (4x4096).
// ---------------------------------------------------------------------------
#define PREP_GRID 25088
__global__ void __launch_bounds__(256) prep_kernel(
    const float* __restrict__ x,
    const float* __restrict__ W0, const float* __restrict__ W1,
    const float* __restrict__ W2, const float* __restrict__ W3,
    __half* __restrict__ xh,
    __half* __restrict__ T0, __half* __restrict__ T1,
    __half* __restrict__ T2, __half* __restrict__ T3,
    float2* __restrict__ sc)
{
    const int blk = blockIdx.x;
    const int tid = threadIdx.x;
    if (blk < 512) {
        const int idx = blk * 256 + tid;          // 2048*64
        const int j = idx & 63;
        const int pos = idx >> 6;
        const double inv = exp(-(double)j * (9.210340371976184 / 64.0));
        const float ang = (float)((double)pos * inv);
        float sn, cs;
        sincosf(ang, &sn, &cs);
        sc[idx] = make_float2(sn, cs);
    } else if (blk < 8704) {
        const int i = (blk - 512) * 256 + tid;    // float4 over x (exact)
        float4 v = ((const float4*)x)[i];
        uint2 r;
        r.x = packh2(v.x, v.y);
        r.y = packh2(v.z, v.w);
        ((uint2*)xh)[i] = r;
    } else {
        const int i2 = blk - 8704;
        const int z = i2 >> 12;                   // 0..3
        const int i = (i2 & 4095) * 256 + tid;    // float4 over weight (exact)
        const float* W = (z == 0) ? W0 : (z == 1) ? W1 : (z == 2) ? W2 : W3;
        __half* Th = (z == 0) ? T0 : (z == 1) ? T1 : (z == 2) ? T2 : T3;
        float4 v = ((const float4*)W)[i];
        uint2 r;
        r.x = packh2(v.x, v.y);
        r.y = packh2(v.z, v.w);
        ((uint2*)Th)[i] = r;
    }
}

// ---------------------------------------------------------------------------
// fp16 GEMM: CTA 128x128x64, 256 threads (8 warps 2m x 4n), warp 64x32,
// 3 cp.async stages x 32KB = 96KB -> 2 CTAs/SM. Compile-time N=K=2048.
// Stage-constant unrolled mainloop (no kt%3 in the hot path).
// Epilogues: Cf -> fp32; sel==2 -> fp16 (V); sel 0/1 -> fused RoPE fp16
// (Q pre-scaled by 1/sqrt(HD)).
// ---------------------------------------------------------------------------
#define G_STAGE 32768
#define G_SMEM  (3 * G_STAGE)

__global__ void __launch_bounds__(256, 2) hgemm1_kernel(
    const __half* __restrict__ Ah,
    const __half* __restrict__ B0, const __half* __restrict__ B1,
    const __half* __restrict__ B2,
    __half* __restrict__ Qout, __half* __restrict__ Kout,
    __half* __restrict__ Vout, float* __restrict__ Cf,
    const float2* __restrict__ T)
{
    extern __shared__ char smem[];
    const uint32_t sbase = smem_u32(smem);

    const int tid = threadIdx.x;
    const int wid = tid >> 5;
    const int lane = tid & 31;
    const int g = lane >> 2;
    const int tig = lane & 3;
    const int warp_m = wid >> 2;
    const int warp_n = wid & 3;
    const int row0 = blockIdx.y * 128;
    const int sel = blockIdx.x >> 4;
    const int col0 = (blockIdx.x & 15) * 128;

    const __half* Bw = (sel == 0) ? B0 : (sel == 1) ? B1 : B2;   // [K][N]
    const __half* Asrc = Ah + (size_t)row0 * DMODEL;
    const __half* Bsrc = Bw + col0;

    auto fill = [&](int kt, int st) {
        const uint32_t sb = sbase + st * G_STAGE;
        const int k0 = kt << 6;
#pragma unroll
        for (int it = 0; it < 8; ++it) {
            const int idx = tid + it * 256;          // 0..2047
            if (idx < 1024) {
                const int r = idx >> 3;              // m row 0..127
                const int ch = idx & 7;
                cp16(sb + r * 128 + ((ch ^ (r & 7)) << 4),
                     Asrc + (size_t)r * DMODEL + k0 + ch * 8);
            } else {
                const int i = idx - 1024;
                const int r = i >> 4;                // k row 0..63
                const int ch = i & 15;
                cp16(sb + 16384 + r * 256 + ((ch ^ (r & 7)) << 4),
                     Bsrc + (size_t)(k0 + r) * DMODEL + ch * 8);
            }
        }
    };

    fill(0, 0); cp_commit();
    fill(1, 1); cp_commit();

    float acc[4][4][4];
#pragma unroll
    for (int mf = 0; mf < 4; ++mf)
#pragma unroll
        for (int nf = 0; nf < 4; ++nf)
#pragma unroll
            for (int r = 0; r < 4; ++r) acc[mf][nf][r] = 0.0f;

    const int a_row = (lane & 7) + ((lane >> 3) & 1) * 8;
    const int a_chs = (lane >> 4) & 1;

    auto compute = [&](int st) {
        const uint32_t sA = sbase + st * G_STAGE;
        const uint32_t sB = sA + 16384;
#pragma unroll
        for (int ks = 0; ks < 4; ++ks) {
            uint32_t bh[4][2];
            {
                const int rl = 16 * ks + (lane & 15);
#pragma unroll
                for (int nfp = 0; nfp < 2; ++nfp) {
                    const int c = warp_n * 4 + 2 * nfp + (lane >> 4);
                    uint32_t b0a, b1a, b0b, b1b;
                    ldsm4t(b0a, b1a, b0b, b1b,
                           sB + rl * 256 + ((c ^ (rl & 7)) << 4));
                    bh[2 * nfp][0] = b0a; bh[2 * nfp][1] = b1a;
                    bh[2 * nfp + 1][0] = b0b; bh[2 * nfp + 1][1] = b1b;
                }
            }
#pragma unroll
            for (int mf = 0; mf < 4; ++mf) {
                const int r = warp_m * 64 + mf * 16 + a_row;
                const int ch = 2 * ks + a_chs;
                uint32_t af[4];
                ldsm4(af[0], af[1], af[2], af[3],
                      sA + r * 128 + ((ch ^ (r & 7)) << 4));
#pragma unroll
                for (int nf = 0; nf < 4; ++nf)
                    mma_f16(acc[mf][nf], af, bh[nf]);
            }
        }
    };

    // main loop: 30 tiles in stage-constant groups of 3, then 2 remainder
#pragma unroll 1
    for (int ktb = 0; ktb < 30; ktb += 3) {
        cp_wait<1>(); __syncthreads();
        fill(ktb + 2, 2); cp_commit();
        compute(0);
        cp_wait<1>(); __syncthreads();
        fill(ktb + 3, 0); cp_commit();
        compute(1);
        cp_wait<1>(); __syncthreads();
        fill(ktb + 4, 1); cp_commit();
        compute(2);
    }
    cp_wait<1>(); __syncthreads();
    compute(0);                      // kt = 30 (stage 0)
    cp_wait<0>(); __syncthreads();
    compute(1);                      // kt = 31 (stage 1)

    if (Cf) {
#pragma unroll
        for (int mf = 0; mf < 4; ++mf) {
            const int row = row0 + warp_m * 64 + mf * 16 + g;
#pragma unroll
            for (int nf = 0; nf < 4; ++nf) {
                const int col = col0 + warp_n * 32 + nf * 8 + 2 * tig;
                *(float2*)&Cf[(size_t)row * DMODEL + col] =
                    make_float2(acc[mf][nf][0], acc[mf][nf][1]);
                *(float2*)&Cf[(size_t)(row + 8) * DMODEL + col] =
                    make_float2(acc[mf][nf][2], acc[mf][nf][3]);
            }
        }
    } else if (sel == 2) {
#pragma unroll
        for (int mf = 0; mf < 4; ++mf) {
            const int row = row0 + warp_m * 64 + mf * 16 + g;
#pragma unroll
            for (int nf = 0; nf < 4; ++nf) {
                const int col = col0 + warp_n * 32 + nf * 8 + 2 * tig;
                *(uint32_t*)&Vout[(size_t)row * DMODEL + col] =
                    packh2(acc[mf][nf][0], acc[mf][nf][1]);
                *(uint32_t*)&Vout[(size_t)(row + 8) * DMODEL + col] =
                    packh2(acc[mf][nf][2], acc[mf][nf][3]);
            }
        }
    } else {
        // Q/K: fused RoPE via smem staging; Q pre-scaled by 1/sqrt(HD)
        __syncthreads();
        float* st = (float*)smem;
#pragma unroll
        for (int mf = 0; mf < 4; ++mf) {
            const int r1 = warp_m * 64 + mf * 16 + g;
#pragma unroll
            for (int nf = 0; nf < 4; ++nf) {
                const int c = warp_n * 32 + nf * 8 + 2 * tig;
                st[r1 * 132 + c]           = acc[mf][nf][0];
                st[r1 * 132 + c + 1]       = acc[mf][nf][1];
                st[(r1 + 8) * 132 + c]     = acc[mf][nf][2];
                st[(r1 + 8) * 132 + c + 1] = acc[mf][nf][3];
            }
        }
        __syncthreads();
        __half* Ch = (sel == 0) ? Qout : Kout;
        const float post = (sel == 0) ? 0.08838834764831845f : 1.0f;
#pragma unroll
        for (int p = 0; p < 16; ++p) {
            const int idx = tid + 256 * p;   // 0..4095
            const int r = idx >> 5;
            const int j = (idx & 31) * 2;
            const float a0 = st[r * 132 + j];
            const float a1 = st[r * 132 + j + 1];
            const float b0 = st[r * 132 + j + 64];
            const float b1 = st[r * 132 + j + 65];
            const int pos = (row0 + r) & (S_LEN - 1);
            const float2 s0 = T[pos * 64 + j];
            const float2 s1 = T[pos * 64 + j + 1];
            const float o00 = (a0 * s0.y - b0 * s0.x) * post;
            const float o10 = (b0 * s0.y + a0 * s0.x) * post;
            const float o01 = (a1 * s1.y - b1 * s1.x) * post;
            const float o11 = (b1 * s1.y + a1 * s1.x) * post;
            const size_t rb = (size_t)(row0 + r) * DMODEL + col0;
            *(uint32_t*)&Ch[rb + j]      = packh2(o00, o01);
            *(uint32_t*)&Ch[rb + j + 64] = packh2(o10, o11);
        }
    }
}

// ---------------------------------------------------------------------------
// Flash attention (causal, tanh-cap via exp identity, sink logit 0).
// Q pre-scaled. K and V both in swizzled 256B-row tiles; K frags via
// ldmatrix.x4, V frags via ldmatrix.x4.trans. P rounded fp16.
// CTA: 128 q-rows x kv-tiles of 64; 8 warps; occ 2.
// ---------------------------------------------------------------------------
#define FQ 0
#define FK 8704                            // Q: 128 x 68 words
#define FV (FK + 2 * 64 * 64)              // K: 2 x (64 rows x 64 words)
#define FLASH_WORDS (FV + 2 * 64 * 64)     // 25088 words
#define FLASH_SMEM (FLASH_WORDS * 4)       // 100352 bytes

__global__ void __launch_bounds__(256, 2) flash_mma_kernel(
    const __half* __restrict__ Q, const __half* __restrict__ K,
    const __half* __restrict__ V, __half* __restrict__ O)
{
    extern __shared__ uint32_t sf[];
    uint32_t* Qs = sf + FQ;
    const uint32_t sbase = smem_u32(sf);

    const int qb = gridDim.x - 1 - blockIdx.x;
    const int h = blockIdx.y;
    const int b = blockIdx.z;
    const int tid = threadIdx.x;
    const int wid = tid >> 5;
    const int lane = tid & 31;
    const int g = lane >> 2;
    const int tig = lane & 3;
    const int q0 = qb * 128;

    const size_t hb = (size_t)b * S_LEN * DMODEL + (size_t)h * HDIM;
    const __half* Qg = Q + hb;
    const __half* Kg = K + hb;
    const __half* Vg = V + hb;

    auto fillKV = [&](int kb) {
        const int k0 = kb * 64;
        const int buf = kb & 1;
        const uint32_t kb_s = sbase + (FK + buf * 64 * 64) * 4;
        const uint32_t vb_s = sbase + (FV + buf * 64 * 64) * 4;
#pragma unroll
        for (int it = 0; it < 4; ++it) {
            const int i = tid + it * 256;        // 0..1023
            const int r = i >> 4;
            const int c = i & 15;
            const uint32_t off = r * 256 + ((c ^ (r & 7)) << 4);
            cp16(kb_s + off, Kg + (size_t)(k0 + r) * DMODEL + c * 8);
            cp16(vb_s + off, Vg + (size_t)(k0 + r) * DMODEL + c * 8);
        }
    };

    // Q tile fill (once)
    for (int i = tid; i < 128 * 16; i += 256) {
        const int r = i >> 4;
        const int ch = i & 15;
        *(uint4*)&Qs[r * 68 + ch * 4] =
            *(const uint4*)&Qg[(size_t)(q0 + r) * DMODEL + ch * 8];
    }

    float o[16][4];
#pragma unroll
    for (int nf = 0; nf < 16; ++nf)
#pragma unroll
        for (int r = 0; r < 4; ++r) o[nf][r] = 0.0f;

    float m0 = 0.0f, m1 = 0.0f;   // sink logit 0
    float l0 = 1.0f, l1 = 1.0f;

    const int mrow0 = wid * 16 + g;
    const int kmax = 2 * qb + 1;
    const int b_row = (lane & 7) + ((lane >> 4) & 1) * 8;
    const int b_chs = (lane >> 3) & 1;

    fillKV(0); cp_commit();

    for (int kb = 0; kb <= kmax; ++kb) {
        cp_wait<0>();
        __syncthreads();
        if (kb < kmax) { fillKV(kb + 1); cp_commit(); }

        const int k0 = kb * 64;
        const int buf = kb & 1;
        const uint32_t kb_s = sbase + (FK + buf * 64 * 64) * 4;
        const uint32_t vb_s = sbase + (FV + buf * 64 * 64) * 4;

        // S = Q K^T (Q pre-scaled); K frags via ldmatrix
        float s[8][4];
#pragma unroll
        for (int nf = 0; nf < 8; ++nf)
#pragma unroll
            for (int r = 0; r < 4; ++r) s[nf][r] = 0.0f;

#pragma unroll
        for (int ks = 0; ks < 8; ++ks) {
            const int kw = 8 * ks + tig;
            uint32_t ah[4];
            const int ra = (wid * 16 + g) * 68;
            const int rb = (wid * 16 + g + 8) * 68;
            ah[0] = Qs[ra + kw];     ah[1] = Qs[rb + kw];
            ah[2] = Qs[ra + kw + 4]; ah[3] = Qs[rb + kw + 4];
            const int ch = 2 * ks + b_chs;
#pragma unroll
            for (int nb = 0; nb < 4; ++nb) {
                const int r = nb * 16 + b_row;
                uint32_t p0, p1, p2, p3;
                ldsm4(p0, p1, p2, p3,
                      kb_s + r * 256 + ((ch ^ (r & 7)) << 4));
                uint32_t bA[2] = { p0, p1 };
                uint32_t bB[2] = { p2, p3 };
                mma_f16(s[2 * nb],     ah, bA);
                mma_f16(s[2 * nb + 1], ah, bB);
            }
        }

        // tanh-cap + causal mask
        const bool need_mask = (kb >= 2 * qb);
        const int grow0 = q0 + mrow0;
        const int grow1 = grow0 + 8;
#pragma unroll
        for (int nf = 0; nf < 8; ++nf) {
#pragma unroll
            for (int r = 0; r < 4; ++r) {
                float v = captanh(s[nf][r]);
                if (need_mask) {
                    const int col = k0 + 8 * nf + 2 * tig + (r & 1);
                    const int row = (r < 2) ? grow0 : grow1;
                    if (col > row) v = -INFINITY;
                }
                s[nf][r] = v;
            }
        }

        // online softmax
        float rmax0 = -3.4e38f, rmax1 = -3.4e38f;
#pragma unroll
        for (int nf = 0; nf < 8; ++nf) {
            rmax0 = fmaxf(rmax0, fmaxf(s[nf][0], s[nf][1]));
            rmax1 = fmaxf(rmax1, fmaxf(s[nf][2], s[nf][3]));
        }
#pragma unroll
        for (int w = 1; w < 4; w <<= 1) {
            rmax0 = fmaxf(rmax0, __shfl_xor_sync(0xffffffffu, rmax0, w));
            rmax1 = fmaxf(rmax1, __shfl_xor_sync(0xffffffffu, rmax1, w));
        }
        const float mn0 = fmaxf(m0, rmax0);
        const float mn1 = fmaxf(m1, rmax1);
        const float cr0 = __expf(m0 - mn0);
        const float cr1 = __expf(m1 - mn1);
        m0 = mn0; m1 = mn1;

        float rs0 = 0.0f, rs1 = 0.0f;
#pragma unroll
        for (int nf = 0; nf < 8; ++nf) {
            s[nf][0] = __expf(s[nf][0] - mn0);
            s[nf][1] = __expf(s[nf][1] - mn0);
            s[nf][2] = __expf(s[nf][2] - mn1);
            s[nf][3] = __expf(s[nf][3] - mn1);
            rs0 += s[nf][0] + s[nf][1];
            rs1 += s[nf][2] + s[nf][3];
        }
#pragma unroll
        for (int w = 1; w < 4; w <<= 1) {
            rs0 += __shfl_xor_sync(0xffffffffu, rs0, w);
            rs1 += __shfl_xor_sync(0xffffffffu, rs1, w);
        }
        l0 = l0 * cr0 + rs0;
        l1 = l1 * cr1 + rs1;

#pragma unroll
        for (int nf = 0; nf < 16; ++nf) {
            o[nf][0] *= cr0; o[nf][1] *= cr0;
            o[nf][2] *= cr1; o[nf][3] *= cr1;
        }

        // O += P V : P rounded fp16; V frags via ldmatrix.trans
#pragma unroll
        for (int ks = 0; ks < 4; ++ks) {
            uint32_t ah[4];
            ah[0] = packh2(s[2 * ks][0],     s[2 * ks][1]);
            ah[1] = packh2(s[2 * ks][2],     s[2 * ks][3]);
            ah[2] = packh2(s[2 * ks + 1][0], s[2 * ks + 1][1]);
            ah[3] = packh2(s[2 * ks + 1][2], s[2 * ks + 1][3]);
            const int rl = 16 * ks + (lane & 15);
#pragma unroll
            for (int nfp = 0; nfp < 8; ++nfp) {
                const int c = 2 * nfp + (lane >> 4);
                uint32_t b0a, b1a, b0b, b1b;
                ldsm4t(b0a, b1a, b0b, b1b,
                       vb_s + rl * 256 + ((c ^ (rl & 7)) << 4));
                uint32_t bA[2] = { b0a, b1a };
                uint32_t bB[2] = { b0b, b1b };
                mma_f16(o[2 * nfp],     ah, bA);
                mma_f16(o[2 * nfp + 1], ah, bB);
            }
        }
    }

    // epilogue: normalize + write fp16 AO plane
    const float inv0 = 1.0f / l0;
    const float inv1 = 1.0f / l1;
    __half* Og = O + hb;
    const int row0g = q0 + wid * 16 + g;
#pragma unroll
    for (int nf = 0; nf < 16; ++nf) {
        const int col = 8 * nf + 2 * tig;
        *(uint32_t*)&Og[(size_t)row0g * DMODEL + col] =
            packh2(o[nf][0] * inv0, o[nf][1] * inv0);
        *(uint32_t*)&Og[(size_t)(row0g + 8) * DMODEL + col] =
            packh2(o[nf][2] * inv1, o[nf][3] * inv1);
    }
}

// ---------------------------------------------------------------------------
extern "C" void kernel_launch(void* const* d_in, const int* in_sizes, int n_in,
                              void* d_out, int out_size)
{
    const float* x  = (const float*)d_in[0];
    const float* Wq = (const float*)d_in[1];
    const float* Wk = (const float*)d_in[2];
    const float* Wv = (const float*)d_in[3];
    const float* Wo = (const float*)d_in[4];
    float* out = (float*)d_out;

    __half *xh, *qh, *kh, *vh, *aoh, *wqh, *wkh, *wvh, *woh;
    float2* sc;
    cudaGetSymbolAddress((void**)&xh,  g_xh);
    cudaGetSymbolAddress((void**)&qh,  g_qh);
    cudaGetSymbolAddress((void**)&kh,  g_kh);
    cudaGetSymbolAddress((void**)&vh,  g_vh);
    cudaGetSymbolAddress((void**)&aoh, g_aoh);
    cudaGetSymbolAddress((void**)&wqh, g_Wqh);
    cudaGetSymbolAddress((void**)&wkh, g_Wkh);
    cudaGetSymbolAddress((void**)&wvh, g_Wvh);
    cudaGetSymbolAddress((void**)&woh, g_Woh);
    cudaGetSymbolAddress((void**)&sc,  g_sc);

    cudaFuncSetAttribute(hgemm1_kernel,
                         cudaFuncAttributeMaxDynamicSharedMemorySize, G_SMEM);
    cudaFuncSetAttribute(flash_mma_kernel,
                         cudaFuncAttributeMaxDynamicSharedMemorySize, FLASH_SMEM);

    // 1. fused prep (one launch)
    prep_kernel<<<PREP_GRID, 256>>>(x, Wq, Wk, Wv, Wo,
                                    xh, wqh, wkh, wvh, woh, sc);

    // 2. fused QKV projection + RoPE epilogue (Q pre-scaled)
    const dim3 gqkv(3 * DMODEL / 128, NTOK / 128);   // (48, 32)
    hgemm1_kernel<<<gqkv, 256, G_SMEM>>>(xh, wqh, wkh, wvh,
                                         qh, kh, vh, nullptr, sc);

    // 3. flash attention
    const dim3 gf(S_LEN / 128, NH, BATCH);           // (16, 16, 2)
    flash_mma_kernel<<<gf, 256, FLASH_SMEM>>>(qh, kh, vh, aoh);

    // 4. output projection (fp32 out)
    const dim3 go(DMODEL / 128, NTOK / 128);         // (16, 32)
    hgemm1_kernel<<<go, 256, G_SMEM>>>(aoh, woh, woh, woh,
                                       nullptr, nullptr, nullptr, out, sc);
}

// round 14
// speedup vs baseline: 1.1904x; 1.0309x over previous
#include <cuda_runtime.h>
#include <cuda_fp16.h>
#include <math.h>
#include <stdint.h>

// Problem constants (B=2, S=2048, D=2048, H=16, HD=128)
#define S_LEN 2048
#define DMODEL 2048
#define NH 16
#define HDIM 128
#define BATCH 2
#define NTOK (BATCH * S_LEN)   // 4096

// ---------------------------------------------------------------------------
// Scratch (__device__ globals; allocation-free rule)
// ---------------------------------------------------------------------------
__device__ __half g_xh[(size_t)NTOK * DMODEL];
__device__ __half g_qh[(size_t)NTOK * DMODEL];    // roped Q fp16 (pre-scaled)
__device__ __half g_kh[(size_t)NTOK * DMODEL];
__device__ __half g_vh[(size_t)NTOK * DMODEL];
__device__ __half g_aoh[(size_t)NTOK * DMODEL];
__device__ __half g_Wqh[(size_t)DMODEL * DMODEL]; // fp16, layout [K][N]
__device__ __half g_Wkh[(size_t)DMODEL * DMODEL];
__device__ __half g_Wvh[(size_t)DMODEL * DMODEL];
__device__ __half g_Woh[(size_t)DMODEL * DMODEL];
__device__ float2 g_sc[(size_t)S_LEN * 64];

// ---------------------------------------------------------------------------
// Helpers
// ---------------------------------------------------------------------------
__device__ __forceinline__ uint32_t packh2(float a, float b) {
    __half2 h = __floats2half2_rn(a, b);
    return *(uint32_t*)&h;
}
__device__ __forceinline__ void mma_f16(float* c, const uint32_t* a,
                                        const uint32_t* b) {
    asm volatile(
        "mma.sync.aligned.m16n8k16.row.col.f32.f16.f16.f32 "
        "{%0,%1,%2,%3}, {%4,%5,%6,%7}, {%8,%9}, {%0,%1,%2,%3};"
        : "+f"(c[0]), "+f"(c[1]), "+f"(c[2]), "+f"(c[3])
        : "r"(a[0]), "r"(a[1]), "r"(a[2]), "r"(a[3]), "r"(b[0]), "r"(b[1]));
}
__device__ __forceinline__ uint32_t smem_u32(const void* p) {
    return (uint32_t)__cvta_generic_to_shared(p);
}
__device__ __forceinline__ void cp16(uint32_t dst, const void* src) {
    asm volatile("cp.async.cg.shared.global [%0], [%1], 16;"
                 :: "r"(dst), "l"(src));
}
__device__ __forceinline__ void cp_commit() {
    asm volatile("cp.async.commit_group;");
}
template <int N>
__device__ __forceinline__ void cp_wait() {
    asm volatile("cp.async.wait_group %0;" :: "n"(N));
}
__device__ __forceinline__ void ldsm4(uint32_t& r0, uint32_t& r1,
                                      uint32_t& r2, uint32_t& r3,
                                      uint32_t addr) {
    asm volatile("ldmatrix.sync.aligned.m8n8.x4.shared.b16 {%0,%1,%2,%3}, [%4];"
                 : "=r"(r0), "=r"(r1), "=r"(r2), "=r"(r3) : "r"(addr));
}
__device__ __forceinline__ void ldsm4t(uint32_t& r0, uint32_t& r1,
                                       uint32_t& r2, uint32_t& r3,
                                       uint32_t addr) {
    asm volatile("ldmatrix.sync.aligned.m8n8.x4.trans.shared.b16 {%0,%1,%2,%3}, [%4];"
                 : "=r"(r0), "=r"(r1), "=r"(r2), "=r"(r3) : "r"(addr));
}
// log2-domain capped tanh: returns log2(e)*[50 - 100/(exp(0.04 v)+1)]
// (exp via exp2: 0.04*log2e = 0.057707802)
__device__ __forceinline__ float captanh2(float v) {
    const float e = exp2f(v * 0.057707802f);
    return 72.13475204f - __fdividef(144.2695041f, e + 1.0f);
}

// ---------------------------------------------------------------------------
// Fused prep: sincos table + x->fp16 + 4 weight converts, one launch.
// ---------------------------------------------------------------------------
#define PREP_GRID 25088
__global__ void __launch_bounds__(256) prep_kernel(
    const float* __restrict__ x,
    const float* __restrict__ W0, const float* __restrict__ W1,
    const float* __restrict__ W2, const float* __restrict__ W3,
    __half* __restrict__ xh,
    __half* __restrict__ T0, __half* __restrict__ T1,
    __half* __restrict__ T2, __half* __restrict__ T3,
    float2* __restrict__ sc)
{
    const int blk = blockIdx.x;
    const int tid = threadIdx.x;
    if (blk < 512) {
        const int idx = blk * 256 + tid;
        const int j = idx & 63;
        const int pos = idx >> 6;
        const double inv = exp(-(double)j * (9.210340371976184 / 64.0));
        const float ang = (float)((double)pos * inv);
        float sn, cs;
        sincosf(ang, &sn, &cs);
        sc[idx] = make_float2(sn, cs);
    } else if (blk < 8704) {
        const int i = (blk - 512) * 256 + tid;
        float4 v = ((const float4*)x)[i];
        uint2 r;
        r.x = packh2(v.x, v.y);
        r.y = packh2(v.z, v.w);
        ((uint2*)xh)[i] = r;
    } else {
        const int i2 = blk - 8704;
        const int z = i2 >> 12;
        const int i = (i2 & 4095) * 256 + tid;
        const float* W = (z == 0) ? W0 : (z == 1) ? W1 : (z == 2) ? W2 : W3;
        __half* Th = (z == 0) ? T0 : (z == 1) ? T1 : (z == 2) ? T2 : T3;
        float4 v = ((const float4*)W)[i];
        uint2 r;
        r.x = packh2(v.x, v.y);
        r.y = packh2(v.z, v.w);
        ((uint2*)Th)[i] = r;
    }
}

// ---------------------------------------------------------------------------
// fp16 GEMM: CTA 128x128x64, 256 threads (8 warps 2m x 4n), warp 64x32,
// 3 cp.async stages x 32KB = 96KB -> 2 CTAs/SM. Compile-time dims.
// Stage-constant unrolled mainloop; B-fragment software pipelining.
// ---------------------------------------------------------------------------
#define G_STAGE 32768
#define G_SMEM  (3 * G_STAGE)

__global__ void __launch_bounds__(256, 2) hgemm1_kernel(
    const __half* __restrict__ Ah,
    const __half* __restrict__ B0, const __half* __restrict__ B1,
    const __half* __restrict__ B2,
    __half* __restrict__ Qout, __half* __restrict__ Kout,
    __half* __restrict__ Vout, float* __restrict__ Cf,
    const float2* __restrict__ T)
{
    extern __shared__ char smem[];
    const uint32_t sbase = smem_u32(smem);

    const int tid = threadIdx.x;
    const int wid = tid >> 5;
    const int lane = tid & 31;
    const int g = lane >> 2;
    const int tig = lane & 3;
    const int warp_m = wid >> 2;
    const int warp_n = wid & 3;
    const int row0 = blockIdx.y * 128;
    const int sel = blockIdx.x >> 4;
    const int col0 = (blockIdx.x & 15) * 128;

    const __half* Bw = (sel == 0) ? B0 : (sel == 1) ? B1 : B2;   // [K][N]
    const __half* Asrc = Ah + (size_t)row0 * DMODEL;
    const __half* Bsrc = Bw + col0;

    auto fill = [&](int kt, int st) {
        const uint32_t sb = sbase + st * G_STAGE;
        const int k0 = kt << 6;
#pragma unroll
        for (int it = 0; it < 8; ++it) {
            const int idx = tid + it * 256;
            if (idx < 1024) {
                const int r = idx >> 3;
                const int ch = idx & 7;
                cp16(sb + r * 128 + ((ch ^ (r & 7)) << 4),
                     Asrc + (size_t)r * DMODEL + k0 + ch * 8);
            } else {
                const int i = idx - 1024;
                const int r = i >> 4;
                const int ch = i & 15;
                cp16(sb + 16384 + r * 256 + ((ch ^ (r & 7)) << 4),
                     Bsrc + (size_t)(k0 + r) * DMODEL + ch * 8);
            }
        }
    };

    fill(0, 0); cp_commit();
    fill(1, 1); cp_commit();

    float acc[4][4][4];
#pragma unroll
    for (int mf = 0; mf < 4; ++mf)
#pragma unroll
        for (int nf = 0; nf < 4; ++nf)
#pragma unroll
            for (int r = 0; r < 4; ++r) acc[mf][nf][r] = 0.0f;

    const int a_row = (lane & 7) + ((lane >> 3) & 1) * 8;
    const int a_chs = (lane >> 4) & 1;
    const int b_rl = lane & 15;
    const int b_cs = lane >> 4;

    auto loadB = [&](const uint32_t sB, int ks, uint32_t bh[4][2]) {
        const int rl = 16 * ks + b_rl;
#pragma unroll
        for (int nfp = 0; nfp < 2; ++nfp) {
            const int c = warp_n * 4 + 2 * nfp + b_cs;
            uint32_t b0a, b1a, b0b, b1b;
            ldsm4t(b0a, b1a, b0b, b1b,
                   sB + rl * 256 + ((c ^ (rl & 7)) << 4));
            bh[2 * nfp][0] = b0a;     bh[2 * nfp][1] = b1a;
            bh[2 * nfp + 1][0] = b0b; bh[2 * nfp + 1][1] = b1b;
        }
    };

    auto compute = [&](int st) {
        const uint32_t sA = sbase + st * G_STAGE;
        const uint32_t sB = sA + 16384;
        uint32_t bcur[4][2], bnext[4][2];
        loadB(sB, 0, bcur);
#pragma unroll
        for (int ks = 0; ks < 4; ++ks) {
            if (ks < 3) loadB(sB, ks + 1, bnext);   // prefetch under MMAs
#pragma unroll
            for (int mf = 0; mf < 4; ++mf) {
                const int r = warp_m * 64 + mf * 16 + a_row;
                const int ch = 2 * ks + a_chs;
                uint32_t af[4];
                ldsm4(af[0], af[1], af[2], af[3],
                      sA + r * 128 + ((ch ^ (r & 7)) << 4));
#pragma unroll
                for (int nf = 0; nf < 4; ++nf)
                    mma_f16(acc[mf][nf], af, bcur[nf]);
            }
#pragma unroll
            for (int nf = 0; nf < 4; ++nf) {
                bcur[nf][0] = bnext[nf][0];
                bcur[nf][1] = bnext[nf][1];
            }
        }
    };

#pragma unroll 1
    for (int ktb = 0; ktb < 30; ktb += 3) {
        cp_wait<1>(); __syncthreads();
        fill(ktb + 2, 2); cp_commit();
        compute(0);
        cp_wait<1>(); __syncthreads();
        fill(ktb + 3, 0); cp_commit();
        compute(1);
        cp_wait<1>(); __syncthreads();
        fill(ktb + 4, 1); cp_commit();
        compute(2);
    }
    cp_wait<1>(); __syncthreads();
    compute(0);
    cp_wait<0>(); __syncthreads();
    compute(1);

    if (Cf) {
#pragma unroll
        for (int mf = 0; mf < 4; ++mf) {
            const int row = row0 + warp_m * 64 + mf * 16 + g;
#pragma unroll
            for (int nf = 0; nf < 4; ++nf) {
                const int col = col0 + warp_n * 32 + nf * 8 + 2 * tig;
                *(float2*)&Cf[(size_t)row * DMODEL + col] =
                    make_float2(acc[mf][nf][0], acc[mf][nf][1]);
                *(float2*)&Cf[(size_t)(row + 8) * DMODEL + col] =
                    make_float2(acc[mf][nf][2], acc[mf][nf][3]);
            }
        }
    } else if (sel == 2) {
#pragma unroll
        for (int mf = 0; mf < 4; ++mf) {
            const int row = row0 + warp_m * 64 + mf * 16 + g;
#pragma unroll
            for (int nf = 0; nf < 4; ++nf) {
                const int col = col0 + warp_n * 32 + nf * 8 + 2 * tig;
                *(uint32_t*)&Vout[(size_t)row * DMODEL + col] =
                    packh2(acc[mf][nf][0], acc[mf][nf][1]);
                *(uint32_t*)&Vout[(size_t)(row + 8) * DMODEL + col] =
                    packh2(acc[mf][nf][2], acc[mf][nf][3]);
            }
        }
    } else {
        // Q/K: fused RoPE via smem staging; Q pre-scaled by 1/sqrt(HD)
        __syncthreads();
        float* st = (float*)smem;
#pragma unroll
        for (int mf = 0; mf < 4; ++mf) {
            const int r1 = warp_m * 64 + mf * 16 + g;
#pragma unroll
            for (int nf = 0; nf < 4; ++nf) {
                const int c = warp_n * 32 + nf * 8 + 2 * tig;
                st[r1 * 132 + c]           = acc[mf][nf][0];
                st[r1 * 132 + c + 1]       = acc[mf][nf][1];
                st[(r1 + 8) * 132 + c]     = acc[mf][nf][2];
                st[(r1 + 8) * 132 + c + 1] = acc[mf][nf][3];
            }
        }
        __syncthreads();
        __half* Ch = (sel == 0) ? Qout : Kout;
        const float post = (sel == 0) ? 0.08838834764831845f : 1.0f;
#pragma unroll
        for (int p = 0; p < 16; ++p) {
            const int idx = tid + 256 * p;
            const int r = idx >> 5;
            const int j = (idx & 31) * 2;
            const float a0 = st[r * 132 + j];
            const float a1 = st[r * 132 + j + 1];
            const float b0 = st[r * 132 + j + 64];
            const float b1 = st[r * 132 + j + 65];
            const int pos = (row0 + r) & (S_LEN - 1);
            const float2 s0 = T[pos * 64 + j];
            const float2 s1 = T[pos * 64 + j + 1];
            const float o00 = (a0 * s0.y - b0 * s0.x) * post;
            const float o10 = (b0 * s0.y + a0 * s0.x) * post;
            const float o01 = (a1 * s1.y - b1 * s1.x) * post;
            const float o11 = (b1 * s1.y + a1 * s1.x) * post;
            const size_t rb = (size_t)(row0 + r) * DMODEL + col0;
            *(uint32_t*)&Ch[rb + j]      = packh2(o00, o01);
            *(uint32_t*)&Ch[rb + j + 64] = packh2(o10, o11);
        }
    }
}

// ---------------------------------------------------------------------------
// Flash attention (causal, tanh-cap, sink logit 0) — log2-domain softmax.
// Q pre-scaled. K frags via ldmatrix.x4, V frags via ldmatrix.x4.trans.
// CTA: 128 q-rows x kv-tiles of 64; 8 warps; occ 2.
// ---------------------------------------------------------------------------
#define FQ 0
#define FK 8704
#define FV (FK + 2 * 64 * 64)
#define FLASH_WORDS (FV + 2 * 64 * 64)
#define FLASH_SMEM (FLASH_WORDS * 4)

__global__ void __launch_bounds__(256, 2) flash_mma_kernel(
    const __half* __restrict__ Q, const __half* __restrict__ K,
    const __half* __restrict__ V, __half* __restrict__ O)
{
    extern __shared__ uint32_t sf[];
    uint32_t* Qs = sf + FQ;
    const uint32_t sbase = smem_u32(sf);

    const int qb = gridDim.x - 1 - blockIdx.x;
    const int h = blockIdx.y;
    const int b = blockIdx.z;
    const int tid = threadIdx.x;
    const int wid = tid >> 5;
    const int lane = tid & 31;
    const int g = lane >> 2;
    const int tig = lane & 3;
    const int q0 = qb * 128;

    const size_t hb = (size_t)b * S_LEN * DMODEL + (size_t)h * HDIM;
    const __half* Qg = Q + hb;
    const __half* Kg = K + hb;
    const __half* Vg = V + hb;

    auto fillKV = [&](int kb) {
        const int k0 = kb * 64;
        const int buf = kb & 1;
        const uint32_t kb_s = sbase + (FK + buf * 64 * 64) * 4;
        const uint32_t vb_s = sbase + (FV + buf * 64 * 64) * 4;
#pragma unroll
        for (int it = 0; it < 4; ++it) {
            const int i = tid + it * 256;
            const int r = i >> 4;
            const int c = i & 15;
            const uint32_t off = r * 256 + ((c ^ (r & 7)) << 4);
            cp16(kb_s + off, Kg + (size_t)(k0 + r) * DMODEL + c * 8);
            cp16(vb_s + off, Vg + (size_t)(k0 + r) * DMODEL + c * 8);
        }
    };

    for (int i = tid; i < 128 * 16; i += 256) {
        const int r = i >> 4;
        const int ch = i & 15;
        *(uint4*)&Qs[r * 68 + ch * 4] =
            *(const uint4*)&Qg[(size_t)(q0 + r) * DMODEL + ch * 8];
    }

    float o[16][4];
#pragma unroll
    for (int nf = 0; nf < 16; ++nf)
#pragma unroll
        for (int r = 0; r < 4; ++r) o[nf][r] = 0.0f;

    // log2-domain state (sink logit 0 -> m=0, l=1)
    float m0 = 0.0f, m1 = 0.0f;
    float l0 = 1.0f, l1 = 1.0f;

    const int mrow0 = wid * 16 + g;
    const int kmax = 2 * qb + 1;
    const int b_row = (lane & 7) + ((lane >> 4) & 1) * 8;
    const int b_chs = (lane >> 3) & 1;

    fillKV(0); cp_commit();

    for (int kb = 0; kb <= kmax; ++kb) {
        cp_wait<0>();
        __syncthreads();
        if (kb < kmax) { fillKV(kb + 1); cp_commit(); }

        const int k0 = kb * 64;
        const int buf = kb & 1;
        const uint32_t kb_s = sbase + (FK + buf * 64 * 64) * 4;
        const uint32_t vb_s = sbase + (FV + buf * 64 * 64) * 4;

        float s[8][4];
#pragma unroll
        for (int nf = 0; nf < 8; ++nf)
#pragma unroll
            for (int r = 0; r < 4; ++r) s[nf][r] = 0.0f;

#pragma unroll
        for (int ks = 0; ks < 8; ++ks) {
            const int kw = 8 * ks + tig;
            uint32_t ah[4];
            const int ra = (wid * 16 + g) * 68;
            const int rb = (wid * 16 + g + 8) * 68;
            ah[0] = Qs[ra + kw];     ah[1] = Qs[rb + kw];
            ah[2] = Qs[ra + kw + 4]; ah[3] = Qs[rb + kw + 4];
            const int ch = 2 * ks + b_chs;
#pragma unroll
            for (int nb = 0; nb < 4; ++nb) {
                const int r = nb * 16 + b_row;
                uint32_t p0, p1, p2, p3;
                ldsm4(p0, p1, p2, p3,
                      kb_s + r * 256 + ((ch ^ (r & 7)) << 4));
                uint32_t bA[2] = { p0, p1 };
                uint32_t bB[2] = { p2, p3 };
                mma_f16(s[2 * nb],     ah, bA);
                mma_f16(s[2 * nb + 1], ah, bB);
            }
        }

        // log2-domain tanh-cap + causal mask
        const bool need_mask = (kb >= 2 * qb);
        const int grow0 = q0 + mrow0;
        const int grow1 = grow0 + 8;
#pragma unroll
        for (int nf = 0; nf < 8; ++nf) {
#pragma unroll
            for (int r = 0; r < 4; ++r) {
                float v = captanh2(s[nf][r]);
                if (need_mask) {
                    const int col = k0 + 8 * nf + 2 * tig + (r & 1);
                    const int row = (r < 2) ? grow0 : grow1;
                    if (col > row) v = -INFINITY;
                }
                s[nf][r] = v;
            }
        }

        float rmax0 = -3.4e38f, rmax1 = -3.4e38f;
#pragma unroll
        for (int nf = 0; nf < 8; ++nf) {
            rmax0 = fmaxf(rmax0, fmaxf(s[nf][0], s[nf][1]));
            rmax1 = fmaxf(rmax1, fmaxf(s[nf][2], s[nf][3]));
        }
#pragma unroll
        for (int w = 1; w < 4; w <<= 1) {
            rmax0 = fmaxf(rmax0, __shfl_xor_sync(0xffffffffu, rmax0, w));
            rmax1 = fmaxf(rmax1, __shfl_xor_sync(0xffffffffu, rmax1, w));
        }
        const float mn0 = fmaxf(m0, rmax0);
        const float mn1 = fmaxf(m1, rmax1);
        const float cr0 = exp2f(m0 - mn0);
        const float cr1 = exp2f(m1 - mn1);
        m0 = mn0; m1 = mn1;

        float rs0 = 0.0f, rs1 = 0.0f;
#pragma unroll
        for (int nf = 0; nf < 8; ++nf) {
            s[nf][0] = exp2f(s[nf][0] - mn0);
            s[nf][1] = exp2f(s[nf][1] - mn0);
            s[nf][2] = exp2f(s[nf][2] - mn1);
            s[nf][3] = exp2f(s[nf][3] - mn1);
            rs0 += s[nf][0] + s[nf][1];
            rs1 += s[nf][2] + s[nf][3];
        }
#pragma unroll
        for (int w = 1; w < 4; w <<= 1) {
            rs0 += __shfl_xor_sync(0xffffffffu, rs0, w);
            rs1 += __shfl_xor_sync(0xffffffffu, rs1, w);
        }
        l0 = l0 * cr0 + rs0;
        l1 = l1 * cr1 + rs1;

#pragma unroll
        for (int nf = 0; nf < 16; ++nf) {
            o[nf][0] *= cr0; o[nf][1] *= cr0;
            o[nf][2] *= cr1; o[nf][3] *= cr1;
        }

#pragma unroll
        for (int ks = 0; ks < 4; ++ks) {
            uint32_t ah[4];
            ah[0] = packh2(s[2 * ks][0],     s[2 * ks][1]);
            ah[1] = packh2(s[2 * ks][2],     s[2 * ks][3]);
            ah[2] = packh2(s[2 * ks + 1][0], s[2 * ks + 1][1]);
            ah[3] = packh2(s[2 * ks + 1][2], s[2 * ks + 1][3]);
            const int rl = 16 * ks + (lane & 15);
#pragma unroll
            for (int nfp = 0; nfp < 8; ++nfp) {
                const int c = 2 * nfp + (lane >> 4);
                uint32_t b0a, b1a, b0b, b1b;
                ldsm4t(b0a, b1a, b0b, b1b,
                       vb_s + rl * 256 + ((c ^ (rl & 7)) << 4));
                uint32_t bA[2] = { b0a, b1a };
                uint32_t bB[2] = { b0b, b1b };
                mma_f16(o[2 * nfp],     ah, bA);
                mma_f16(o[2 * nfp + 1], ah, bB);
            }
        }
    }

    const float inv0 = 1.0f / l0;
    const float inv1 = 1.0f / l1;
    __half* Og = O + hb;
    const int row0g = q0 + wid * 16 + g;
#pragma unroll
    for (int nf = 0; nf < 16; ++nf) {
        const int col = 8 * nf + 2 * tig;
        *(uint32_t*)&Og[(size_t)row0g * DMODEL + col] =
            packh2(o[nf][0] * inv0, o[nf][1] * inv0);
        *(uint32_t*)&Og[(size_t)(row0g + 8) * DMODEL + col] =
            packh2(o[nf][2] * inv1, o[nf][3] * inv1);
    }
}

// ---------------------------------------------------------------------------
extern "C" void kernel_launch(void* const* d_in, const int* in_sizes, int n_in,
                              void* d_out, int out_size)
{
    const float* x  = (const float*)d_in[0];
    const float* Wq = (const float*)d_in[1];
    const float* Wk = (const float*)d_in[2];
    const float* Wv = (const float*)d_in[3];
    const float* Wo = (const float*)d_in[4];
    float* out = (float*)d_out;

    __half *xh, *qh, *kh, *vh, *aoh, *wqh, *wkh, *wvh, *woh;
    float2* sc;
    cudaGetSymbolAddress((void**)&xh,  g_xh);
    cudaGetSymbolAddress((void**)&qh,  g_qh);
    cudaGetSymbolAddress((void**)&kh,  g_kh);
    cudaGetSymbolAddress((void**)&vh,  g_vh);
    cudaGetSymbolAddress((void**)&aoh, g_aoh);
    cudaGetSymbolAddress((void**)&wqh, g_Wqh);
    cudaGetSymbolAddress((void**)&wkh, g_Wkh);
    cudaGetSymbolAddress((void**)&wvh, g_Wvh);
    cudaGetSymbolAddress((void**)&woh, g_Woh);
    cudaGetSymbolAddress((void**)&sc,  g_sc);

    cudaFuncSetAttribute(hgemm1_kernel,
                         cudaFuncAttributeMaxDynamicSharedMemorySize, G_SMEM);
    cudaFuncSetAttribute(flash_mma_kernel,
                         cudaFuncAttributeMaxDynamicSharedMemorySize, FLASH_SMEM);

    // 1. fused prep
    prep_kernel<<<PREP_GRID, 256>>>(x, Wq, Wk, Wv, Wo,
                                    xh, wqh, wkh, wvh, woh, sc);

    // 2. fused QKV projection + RoPE epilogue (Q pre-scaled)
    const dim3 gqkv(3 * DMODEL / 128, NTOK / 128);   // (48, 32)
    hgemm1_kernel<<<gqkv, 256, G_SMEM>>>(xh, wqh, wkh, wvh,
                                         qh, kh, vh, nullptr, sc);

    // 3. flash attention
    const dim3 gf(S_LEN / 128, NH, BATCH);           // (16, 16, 2)
    flash_mma_kernel<<<gf, 256, FLASH_SMEM>>>(qh, kh, vh, aoh);

    // 4. output projection (fp32 out)
    const dim3 go(DMODEL / 128, NTOK / 128);         // (16, 32)
    hgemm1_kernel<<<go, 256, G_SMEM>>>(aoh, woh, woh, woh,
                                       nullptr, nullptr, nullptr, out, sc);
}

// round 16
// speedup vs baseline: 1.2020x; 1.0098x over previous
#include <cuda_runtime.h>
#include <cuda_fp16.h>
#include <math.h>
#include <stdint.h>

// Problem constants (B=2, S=2048, D=2048, H=16, HD=128)
#define S_LEN 2048
#define DMODEL 2048
#define NH 16
#define HDIM 128
#define BATCH 2
#define NTOK (BATCH * S_LEN)   // 4096

// ---------------------------------------------------------------------------
// Scratch (__device__ globals; allocation-free rule)
// ---------------------------------------------------------------------------
__device__ __half g_xh[(size_t)NTOK * DMODEL];
__device__ __half g_qh[(size_t)NTOK * DMODEL];    // roped Q fp16 (pre-scaled)
__device__ __half g_kh[(size_t)NTOK * DMODEL];
__device__ __half g_vh[(size_t)NTOK * DMODEL];
__device__ __half g_aoh[(size_t)NTOK * DMODEL];
__device__ __half g_Wqh[(size_t)DMODEL * DMODEL]; // fp16, layout [K][N]
__device__ __half g_Wkh[(size_t)DMODEL * DMODEL];
__device__ __half g_Wvh[(size_t)DMODEL * DMODEL];
__device__ __half g_Woh[(size_t)DMODEL * DMODEL];
__device__ float2 g_sc[(size_t)S_LEN * 64];

// ---------------------------------------------------------------------------
// Helpers
// ---------------------------------------------------------------------------
__device__ __forceinline__ uint32_t packh2(float a, float b) {
    __half2 h = __floats2half2_rn(a, b);
    return *(uint32_t*)&h;
}
__device__ __forceinline__ void mma_f16(float* c, const uint32_t* a,
                                        const uint32_t* b) {
    asm volatile(
        "mma.sync.aligned.m16n8k16.row.col.f32.f16.f16.f32 "
        "{%0,%1,%2,%3}, {%4,%5,%6,%7}, {%8,%9}, {%0,%1,%2,%3};"
        : "+f"(c[0]), "+f"(c[1]), "+f"(c[2]), "+f"(c[3])
        : "r"(a[0]), "r"(a[1]), "r"(a[2]), "r"(a[3]), "r"(b[0]), "r"(b[1]));
}
__device__ __forceinline__ uint32_t smem_u32(const void* p) {
    return (uint32_t)__cvta_generic_to_shared(p);
}
__device__ __forceinline__ void cp16(uint32_t dst, const void* src) {
    asm volatile("cp.async.cg.shared.global [%0], [%1], 16;"
                 :: "r"(dst), "l"(src));
}
__device__ __forceinline__ void cp_commit() {
    asm volatile("cp.async.commit_group;");
}
template <int N>
__device__ __forceinline__ void cp_wait() {
    asm volatile("cp.async.wait_group %0;" :: "n"(N));
}
__device__ __forceinline__ void ldsm4(uint32_t& r0, uint32_t& r1,
                                      uint32_t& r2, uint32_t& r3,
                                      uint32_t addr) {
    asm volatile("ldmatrix.sync.aligned.m8n8.x4.shared.b16 {%0,%1,%2,%3}, [%4];"
                 : "=r"(r0), "=r"(r1), "=r"(r2), "=r"(r3) : "r"(addr));
}
__device__ __forceinline__ void ldsm4t(uint32_t& r0, uint32_t& r1,
                                       uint32_t& r2, uint32_t& r3,
                                       uint32_t addr) {
    asm volatile("ldmatrix.sync.aligned.m8n8.x4.trans.shared.b16 {%0,%1,%2,%3}, [%4];"
                 : "=r"(r0), "=r"(r1), "=r"(r2), "=r"(r3) : "r"(addr));
}
// log2-domain capped tanh: log2(e)*[50 - 100/(exp(0.04 v)+1)]
__device__ __forceinline__ float captanh2(float v) {
    const float e = exp2f(v * 0.057707802f);
    return 72.13475204f - __fdividef(144.2695041f, e + 1.0f);
}

// ---------------------------------------------------------------------------
// Fused prep: sincos table + x->fp16 + 4 weight converts, one launch.
// ---------------------------------------------------------------------------
#define PREP_GRID 25088
__global__ void __launch_bounds__(256) prep_kernel(
    const float* __restrict__ x,
    const float* __restrict__ W0, const float* __restrict__ W1,
    const float* __restrict__ W2, const float* __restrict__ W3,
    __half* __restrict__ xh,
    __half* __restrict__ T0, __half* __restrict__ T1,
    __half* __restrict__ T2, __half* __restrict__ T3,
    float2* __restrict__ sc)
{
    const int blk = blockIdx.x;
    const int tid = threadIdx.x;
    if (blk < 512) {
        const int idx = blk * 256 + tid;
        const int j = idx & 63;
        const int pos = idx >> 6;
        const double inv = exp(-(double)j * (9.210340371976184 / 64.0));
        const float ang = (float)((double)pos * inv);
        float sn, cs;
        sincosf(ang, &sn, &cs);
        sc[idx] = make_float2(sn, cs);
    } else if (blk < 8704) {
        const int i = (blk - 512) * 256 + tid;
        float4 v = ((const float4*)x)[i];
        uint2 r;
        r.x = packh2(v.x, v.y);
        r.y = packh2(v.z, v.w);
        ((uint2*)xh)[i] = r;
    } else {
        const int i2 = blk - 8704;
        const int z = i2 >> 12;
        const int i = (i2 & 4095) * 256 + tid;
        const float* W = (z == 0) ? W0 : (z == 1) ? W1 : (z == 2) ? W2 : W3;
        __half* Th = (z == 0) ? T0 : (z == 1) ? T1 : (z == 2) ? T2 : T3;
        float4 v = ((const float4*)W)[i];
        uint2 r;
        r.x = packh2(v.x, v.y);
        r.y = packh2(v.z, v.w);
        ((uint2*)Th)[i] = r;
    }
}

// ---------------------------------------------------------------------------
// fp16 GEMM: CTA 128x128x64, 256 threads (8 warps 2m x 4n), warp 64x32,
// 3 cp.async stages x 32KB = 96KB -> 2 CTAs/SM. Compile-time dims.
// R14-proven ordering: wait -> sync -> fill -> commit -> compute.
// B-fragment software pipelining inside compute.
// ---------------------------------------------------------------------------
#define G_STAGE 32768
#define G_SMEM  (3 * G_STAGE)

__global__ void __launch_bounds__(256, 2) hgemm1_kernel(
    const __half* __restrict__ Ah,
    const __half* __restrict__ B0, const __half* __restrict__ B1,
    const __half* __restrict__ B2,
    __half* __restrict__ Qout, __half* __restrict__ Kout,
    __half* __restrict__ Vout, float* __restrict__ Cf,
    const float2* __restrict__ T)
{
    extern __shared__ char smem[];
    const uint32_t sbase = smem_u32(smem);

    const int tid = threadIdx.x;
    const int wid = tid >> 5;
    const int lane = tid & 31;
    const int g = lane >> 2;
    const int tig = lane & 3;
    const int warp_m = wid >> 2;
    const int warp_n = wid & 3;
    const int row0 = blockIdx.y * 128;
    const int sel = blockIdx.x >> 4;
    const int col0 = (blockIdx.x & 15) * 128;

    const __half* Bw = (sel == 0) ? B0 : (sel == 1) ? B1 : B2;   // [K][N]
    const __half* Asrc = Ah + (size_t)row0 * DMODEL;
    const __half* Bsrc = Bw + col0;

    auto fill = [&](int kt, int st) {
        const uint32_t sb = sbase + st * G_STAGE;
        const int k0 = kt << 6;
#pragma unroll
        for (int it = 0; it < 8; ++it) {
            const int idx = tid + it * 256;
            if (idx < 1024) {
                const int r = idx >> 3;
                const int ch = idx & 7;
                cp16(sb + r * 128 + ((ch ^ (r & 7)) << 4),
                     Asrc + (size_t)r * DMODEL + k0 + ch * 8);
            } else {
                const int i = idx - 1024;
                const int r = i >> 4;
                const int ch = i & 15;
                cp16(sb + 16384 + r * 256 + ((ch ^ (r & 7)) << 4),
                     Bsrc + (size_t)(k0 + r) * DMODEL + ch * 8);
            }
        }
    };

    fill(0, 0); cp_commit();
    fill(1, 1); cp_commit();

    float acc[4][4][4];
#pragma unroll
    for (int mf = 0; mf < 4; ++mf)
#pragma unroll
        for (int nf = 0; nf < 4; ++nf)
#pragma unroll
            for (int r = 0; r < 4; ++r) acc[mf][nf][r] = 0.0f;

    const int a_row = (lane & 7) + ((lane >> 3) & 1) * 8;
    const int a_chs = (lane >> 4) & 1;
    const int b_rl = lane & 15;
    const int b_cs = lane >> 4;

    auto loadB = [&](const uint32_t sB, int ks, uint32_t bh[4][2]) {
        const int rl = 16 * ks + b_rl;
#pragma unroll
        for (int nfp = 0; nfp < 2; ++nfp) {
            const int c = warp_n * 4 + 2 * nfp + b_cs;
            uint32_t b0a, b1a, b0b, b1b;
            ldsm4t(b0a, b1a, b0b, b1b,
                   sB + rl * 256 + ((c ^ (rl & 7)) << 4));
            bh[2 * nfp][0] = b0a;     bh[2 * nfp][1] = b1a;
            bh[2 * nfp + 1][0] = b0b; bh[2 * nfp + 1][1] = b1b;
        }
    };

    auto compute = [&](int st) {
        const uint32_t sA = sbase + st * G_STAGE;
        const uint32_t sB = sA + 16384;
        uint32_t bcur[4][2], bnext[4][2];
        loadB(sB, 0, bcur);
#pragma unroll
        for (int ks = 0; ks < 4; ++ks) {
            if (ks < 3) loadB(sB, ks + 1, bnext);
#pragma unroll
            for (int mf = 0; mf < 4; ++mf) {
                const int r = warp_m * 64 + mf * 16 + a_row;
                const int ch = 2 * ks + a_chs;
                uint32_t af[4];
                ldsm4(af[0], af[1], af[2], af[3],
                      sA + r * 128 + ((ch ^ (r & 7)) << 4));
#pragma unroll
                for (int nf = 0; nf < 4; ++nf)
                    mma_f16(acc[mf][nf], af, bcur[nf]);
            }
#pragma unroll
            for (int nf = 0; nf < 4; ++nf) {
                bcur[nf][0] = bnext[nf][0];
                bcur[nf][1] = bnext[nf][1];
            }
        }
    };

    // R14-proven mainloop: wait -> sync -> fill -> commit -> compute
#pragma unroll 1
    for (int ktb = 0; ktb < 30; ktb += 3) {
        cp_wait<1>(); __syncthreads();
        fill(ktb + 2, 2); cp_commit();
        compute(0);
        cp_wait<1>(); __syncthreads();
        fill(ktb + 3, 0); cp_commit();
        compute(1);
        cp_wait<1>(); __syncthreads();
        fill(ktb + 4, 1); cp_commit();
        compute(2);
    }
    cp_wait<1>(); __syncthreads();
    compute(0);                      // kt = 30 (stage 0)
    cp_wait<0>(); __syncthreads();
    compute(1);                      // kt = 31 (stage 1)

    if (Cf) {
#pragma unroll
        for (int mf = 0; mf < 4; ++mf) {
            const int row = row0 + warp_m * 64 + mf * 16 + g;
#pragma unroll
            for (int nf = 0; nf < 4; ++nf) {
                const int col = col0 + warp_n * 32 + nf * 8 + 2 * tig;
                *(float2*)&Cf[(size_t)row * DMODEL + col] =
                    make_float2(acc[mf][nf][0], acc[mf][nf][1]);
                *(float2*)&Cf[(size_t)(row + 8) * DMODEL + col] =
                    make_float2(acc[mf][nf][2], acc[mf][nf][3]);
            }
        }
    } else if (sel == 2) {
#pragma unroll
        for (int mf = 0; mf < 4; ++mf) {
            const int row = row0 + warp_m * 64 + mf * 16 + g;
#pragma unroll
            for (int nf = 0; nf < 4; ++nf) {
                const int col = col0 + warp_n * 32 + nf * 8 + 2 * tig;
                *(uint32_t*)&Vout[(size_t)row * DMODEL + col] =
                    packh2(acc[mf][nf][0], acc[mf][nf][1]);
                *(uint32_t*)&Vout[(size_t)(row + 8) * DMODEL + col] =
                    packh2(acc[mf][nf][2], acc[mf][nf][3]);
            }
        }
    } else {
        // Q/K: fused RoPE via smem staging; Q pre-scaled by 1/sqrt(HD)
        __syncthreads();
        float* st = (float*)smem;
#pragma unroll
        for (int mf = 0; mf < 4; ++mf) {
            const int r1 = warp_m * 64 + mf * 16 + g;
#pragma unroll
            for (int nf = 0; nf < 4; ++nf) {
                const int c = warp_n * 32 + nf * 8 + 2 * tig;
                st[r1 * 132 + c]           = acc[mf][nf][0];
                st[r1 * 132 + c + 1]       = acc[mf][nf][1];
                st[(r1 + 8) * 132 + c]     = acc[mf][nf][2];
                st[(r1 + 8) * 132 + c + 1] = acc[mf][nf][3];
            }
        }
        __syncthreads();
        __half* Ch = (sel == 0) ? Qout : Kout;
        const float post = (sel == 0) ? 0.08838834764831845f : 1.0f;
#pragma unroll
        for (int p = 0; p < 16; ++p) {
            const int idx = tid + 256 * p;
            const int r = idx >> 5;
            const int j = (idx & 31) * 2;
            const float a0 = st[r * 132 + j];
            const float a1 = st[r * 132 + j + 1];
            const float b0 = st[r * 132 + j + 64];
            const float b1 = st[r * 132 + j + 65];
            const int pos = (row0 + r) & (S_LEN - 1);
            const float2 s0 = T[pos * 64 + j];
            const float2 s1 = T[pos * 64 + j + 1];
            const float o00 = (a0 * s0.y - b0 * s0.x) * post;
            const float o10 = (b0 * s0.y + a0 * s0.x) * post;
            const float o01 = (a1 * s1.y - b1 * s1.x) * post;
            const float o11 = (b1 * s1.y + a1 * s1.x) * post;
            const size_t rb = (size_t)(row0 + r) * DMODEL + col0;
            *(uint32_t*)&Ch[rb + j]      = packh2(o00, o01);
            *(uint32_t*)&Ch[rb + j + 64] = packh2(o10, o11);
        }
    }
}

// ---------------------------------------------------------------------------
// Flash attention (causal, tanh-cap, sink logit 0) — log2-domain softmax.
// Q pre-scaled; Q and K frags via ldmatrix.x4, V frags via ldmatrix.x4.trans.
// R14-proven ordering: wait -> sync -> fill(next) -> commit -> compute.
// CTA: 128 q-rows x kv-tiles of 64; 8 warps; occ 2.
// ---------------------------------------------------------------------------
#define FQ 0
#define FK 8704
#define FV (FK + 2 * 64 * 64)
#define FLASH_WORDS (FV + 2 * 64 * 64)
#define FLASH_SMEM (FLASH_WORDS * 4)

__global__ void __launch_bounds__(256, 2) flash_mma_kernel(
    const __half* __restrict__ Q, const __half* __restrict__ K,
    const __half* __restrict__ V, __half* __restrict__ O)
{
    extern __shared__ uint32_t sf[];
    uint32_t* Qs = sf + FQ;
    const uint32_t sbase = smem_u32(sf);

    const int qb = gridDim.x - 1 - blockIdx.x;
    const int h = blockIdx.y;
    const int b = blockIdx.z;
    const int tid = threadIdx.x;
    const int wid = tid >> 5;
    const int lane = tid & 31;
    const int g = lane >> 2;
    const int tig = lane & 3;
    const int q0 = qb * 128;

    const size_t hb = (size_t)b * S_LEN * DMODEL + (size_t)h * HDIM;
    const __half* Qg = Q + hb;
    const __half* Kg = K + hb;
    const __half* Vg = V + hb;

    auto fillKV = [&](int kb) {
        const int k0 = kb * 64;
        const int buf = kb & 1;
        const uint32_t kb_s = sbase + (FK + buf * 64 * 64) * 4;
        const uint32_t vb_s = sbase + (FV + buf * 64 * 64) * 4;
#pragma unroll
        for (int it = 0; it < 4; ++it) {
            const int i = tid + it * 256;
            const int r = i >> 4;
            const int c = i & 15;
            const uint32_t off = r * 256 + ((c ^ (r & 7)) << 4);
            cp16(kb_s + off, Kg + (size_t)(k0 + r) * DMODEL + c * 8);
            cp16(vb_s + off, Vg + (size_t)(k0 + r) * DMODEL + c * 8);
        }
    };

    for (int i = tid; i < 128 * 16; i += 256) {
        const int r = i >> 4;
        const int ch = i & 15;
        *(uint4*)&Qs[r * 68 + ch * 4] =
            *(const uint4*)&Qg[(size_t)(q0 + r) * DMODEL + ch * 8];
    }

    float o[16][4];
#pragma unroll
    for (int nf = 0; nf < 16; ++nf)
#pragma unroll
        for (int r = 0; r < 4; ++r) o[nf][r] = 0.0f;

    float m0 = 0.0f, m1 = 0.0f;   // log2-domain; sink logit 0
    float l0 = 1.0f, l1 = 1.0f;

    const int mrow0 = wid * 16 + g;
    const int kmax = 2 * qb + 1;
    const int a_row = (lane & 7) + ((lane >> 3) & 1) * 8;
    const int a_chs = (lane >> 4) & 1;
    const int b_row = (lane & 7) + ((lane >> 4) & 1) * 8;
    const int b_chs = (lane >> 3) & 1;

    fillKV(0); cp_commit();

    for (int kb = 0; kb <= kmax; ++kb) {
        cp_wait<0>();
        __syncthreads();
        if (kb < kmax) { fillKV(kb + 1); cp_commit(); }

        const int k0 = kb * 64;
        const int buf = kb & 1;
        const uint32_t kb_s = sbase + (FK + buf * 64 * 64) * 4;
        const uint32_t vb_s = sbase + (FV + buf * 64 * 64) * 4;

        // S = Q K^T; Q and K frags via ldmatrix.x4
        float s[8][4];
#pragma unroll
        for (int nf = 0; nf < 8; ++nf)
#pragma unroll
            for (int r = 0; r < 4; ++r) s[nf][r] = 0.0f;

#pragma unroll
        for (int ks = 0; ks < 8; ++ks) {
            uint32_t ah[4];
            {
                const int r = wid * 16 + a_row;
                ldsm4(ah[0], ah[1], ah[2], ah[3],
                      sbase + (r * 68 + (2 * ks + a_chs) * 4) * 4);
            }
            const int ch = 2 * ks + b_chs;
#pragma unroll
            for (int nb = 0; nb < 4; ++nb) {
                const int r = nb * 16 + b_row;
                uint32_t p0, p1, p2, p3;
                ldsm4(p0, p1, p2, p3,
                      kb_s + r * 256 + ((ch ^ (r & 7)) << 4));
                uint32_t bA[2] = { p0, p1 };
                uint32_t bB[2] = { p2, p3 };
                mma_f16(s[2 * nb],     ah, bA);
                mma_f16(s[2 * nb + 1], ah, bB);
            }
        }

        // log2-domain tanh-cap + causal mask
        const bool need_mask = (kb >= 2 * qb);
        const int grow0 = q0 + mrow0;
        const int grow1 = grow0 + 8;
#pragma unroll
        for (int nf = 0; nf < 8; ++nf) {
#pragma unroll
            for (int r = 0; r < 4; ++r) {
                float v = captanh2(s[nf][r]);
                if (need_mask) {
                    const int col = k0 + 8 * nf + 2 * tig + (r & 1);
                    const int row = (r < 2) ? grow0 : grow1;
                    if (col > row) v = -INFINITY;
                }
                s[nf][r] = v;
            }
        }

        float rmax0 = -3.4e38f, rmax1 = -3.4e38f;
#pragma unroll
        for (int nf = 0; nf < 8; ++nf) {
            rmax0 = fmaxf(rmax0, fmaxf(s[nf][0], s[nf][1]));
            rmax1 = fmaxf(rmax1, fmaxf(s[nf][2], s[nf][3]));
        }
#pragma unroll
        for (int w = 1; w < 4; w <<= 1) {
            rmax0 = fmaxf(rmax0, __shfl_xor_sync(0xffffffffu, rmax0, w));
            rmax1 = fmaxf(rmax1, __shfl_xor_sync(0xffffffffu, rmax1, w));
        }
        const float mn0 = fmaxf(m0, rmax0);
        const float mn1 = fmaxf(m1, rmax1);
        const float cr0 = exp2f(m0 - mn0);
        const float cr1 = exp2f(m1 - mn1);
        m0 = mn0; m1 = mn1;

        float rs0 = 0.0f, rs1 = 0.0f;
#pragma unroll
        for (int nf = 0; nf < 8; ++nf) {
            s[nf][0] = exp2f(s[nf][0] - mn0);
            s[nf][1] = exp2f(s[nf][1] - mn0);
            s[nf][2] = exp2f(s[nf][2] - mn1);
            s[nf][3] = exp2f(s[nf][3] - mn1);
            rs0 += s[nf][0] + s[nf][1];
            rs1 += s[nf][2] + s[nf][3];
        }
#pragma unroll
        for (int w = 1; w < 4; w <<= 1) {
            rs0 += __shfl_xor_sync(0xffffffffu, rs0, w);
            rs1 += __shfl_xor_sync(0xffffffffu, rs1, w);
        }
        l0 = l0 * cr0 + rs0;
        l1 = l1 * cr1 + rs1;

#pragma unroll
        for (int nf = 0; nf < 16; ++nf) {
            o[nf][0] *= cr0; o[nf][1] *= cr0;
            o[nf][2] *= cr1; o[nf][3] *= cr1;
        }

#pragma unroll
        for (int ks = 0; ks < 4; ++ks) {
            uint32_t ah[4];
            ah[0] = packh2(s[2 * ks][0],     s[2 * ks][1]);
            ah[1] = packh2(s[2 * ks][2],     s[2 * ks][3]);
            ah[2] = packh2(s[2 * ks + 1][0], s[2 * ks + 1][1]);
            ah[3] = packh2(s[2 * ks + 1][2], s[2 * ks + 1][3]);
            const int rl = 16 * ks + (lane & 15);
#pragma unroll
            for (int nfp = 0; nfp < 8; ++nfp) {
                const int c = 2 * nfp + (lane >> 4);
                uint32_t b0a, b1a, b0b, b1b;
                ldsm4t(b0a, b1a, b0b, b1b,
                       vb_s + rl * 256 + ((c ^ (rl & 7)) << 4));
                uint32_t bA[2] = { b0a, b1a };
                uint32_t bB[2] = { b0b, b1b };
                mma_f16(o[2 * nfp],     ah, bA);
                mma_f16(o[2 * nfp + 1], ah, bB);
            }
        }
    }

    const float inv0 = 1.0f / l0;
    const float inv1 = 1.0f / l1;
    __half* Og = O + hb;
    const int row0g = q0 + wid * 16 + g;
#pragma unroll
    for (int nf = 0; nf < 16; ++nf) {
        const int col = 8 * nf + 2 * tig;
        *(uint32_t*)&Og[(size_t)row0g * DMODEL + col] =
            packh2(o[nf][0] * inv0, o[nf][1] * inv0);
        *(uint32_t*)&Og[(size_t)(row0g + 8) * DMODEL + col] =
            packh2(o[nf][2] * inv1, o[nf][3] * inv1);
    }
}

// ---------------------------------------------------------------------------
extern "C" void kernel_launch(void* const* d_in, const int* in_sizes, int n_in,
                              void* d_out, int out_size)
{
    const float* x  = (const float*)d_in[0];
    const float* Wq = (const float*)d_in[1];
    const float* Wk = (const float*)d_in[2];
    const float* Wv = (const float*)d_in[3];
    const float* Wo = (const float*)d_in[4];
    float* out = (float*)d_out;

    __half *xh, *qh, *kh, *vh, *aoh, *wqh, *wkh, *wvh, *woh;
    float2* sc;
    cudaGetSymbolAddress((void**)&xh,  g_xh);
    cudaGetSymbolAddress((void**)&qh,  g_qh);
    cudaGetSymbolAddress((void**)&kh,  g_kh);
    cudaGetSymbolAddress((void**)&vh,  g_vh);
    cudaGetSymbolAddress((void**)&aoh, g_aoh);
    cudaGetSymbolAddress((void**)&wqh, g_Wqh);
    cudaGetSymbolAddress((void**)&wkh, g_Wkh);
    cudaGetSymbolAddress((void**)&wvh, g_Wvh);
    cudaGetSymbolAddress((void**)&woh, g_Woh);
    cudaGetSymbolAddress((void**)&sc,  g_sc);

    cudaFuncSetAttribute(hgemm1_kernel,
                         cudaFuncAttributeMaxDynamicSharedMemorySize, G_SMEM);
    cudaFuncSetAttribute(flash_mma_kernel,
                         cudaFuncAttributeMaxDynamicSharedMemorySize, FLASH_SMEM);

    // 1. fused prep
    prep_kernel<<<PREP_GRID, 256>>>(x, Wq, Wk, Wv, Wo,
                                    xh, wqh, wkh, wvh, woh, sc);

    // 2. fused QKV projection + RoPE epilogue (Q pre-scaled)
    const dim3 gqkv(3 * DMODEL / 128, NTOK / 128);   // (48, 32)
    hgemm1_kernel<<<gqkv, 256, G_SMEM>>>(xh, wqh, wkh, wvh,
                                         qh, kh, vh, nullptr, sc);

    // 3. flash attention
    const dim3 gf(S_LEN / 128, NH, BATCH);           // (16, 16, 2)
    flash_mma_kernel<<<gf, 256, FLASH_SMEM>>>(qh, kh, vh, aoh);

    // 4. output projection (fp32 out)
    const dim3 go(DMODEL / 128, NTOK / 128);         // (16, 32)
    hgemm1_kernel<<<go, 256, G_SMEM>>>(aoh, woh, woh, woh,
                                       nullptr, nullptr, nullptr, out, sc);
}